// round 6
// baseline (speedup 1.0000x reference)
#include <cuda_runtime.h>
#include <cuda_bf16.h>
#include <math.h>

// ---------------------------------------------------------------------------
// PairwiseMLPLinkPredictor — GB300 sm_103a
//
// Inputs (metadata order):
//  0: x          float32 [8192*128]
//  1: edge_index int32   [2*262144]   (JAX x64 disabled -> int64 request lands as int32;
//                                      confirmed by R1 crash signature under int64 reads)
//  2: edge_pairs int32   [65536*2]
//  3: W1 float32 [644*256]   4: b1 [256]
//  5: W2 float32 [256*128]   6: b2 [128]
//  7: W3 float32 [128]       8: b3 [1]
// Output: float32 [65536]
// ---------------------------------------------------------------------------

#define NNODES   8192
#define WORDS    128          // 8192 bits / 64
#define INCH     128
#define HID      256
#define HID2     128
#define TBP      64           // pairs per block in main kernel
#define EPSF     1e-8f

// --------------------------- device scratch --------------------------------
__device__ unsigned long long g_bits[(size_t)NNODES * WORDS];   // 8 MB
__device__ float g_invlog[NNODES];
__device__ float g_invdeg[NNODES];
__device__ float g_norm[NNODES];
__device__ float g_Wa[INCH * HID];                              // W1[0:128]+W1[512:640]
__device__ float g_Wb[INCH * HID];                              // W1[128:256]+W1[512:640]
__device__ float g_preu[(size_t)NNODES * HID];                  // x @ Wa  (8 MB)
__device__ float g_prev[(size_t)NNODES * HID];                  // x @ Wb  (8 MB)

// --------------------------- f32x2 helpers ---------------------------------
__device__ __forceinline__ unsigned long long pk2(float a) {
    unsigned long long r;
    unsigned int ai = __float_as_uint(a);
    asm("mov.b64 %0, {%1, %1};" : "=l"(r) : "r"(ai));
    return r;
}
__device__ __forceinline__ unsigned long long fma2(unsigned long long a,
                                                   unsigned long long b,
                                                   unsigned long long c) {
    unsigned long long d;
    asm("fma.rn.f32x2 %0, %1, %2, %3;" : "=l"(d) : "l"(a), "l"(b), "l"(c));
    return d;
}
__device__ __forceinline__ float lo2(unsigned long long v) {
    return __uint_as_float((unsigned int)v);
}
__device__ __forceinline__ float hi2(unsigned long long v) {
    return __uint_as_float((unsigned int)(v >> 32));
}

// --------------------------- prep kernels ----------------------------------
__global__ void build_bits_kernel(const int* __restrict__ ei, int E) {
    int e = blockIdx.x * blockDim.x + threadIdx.x;
    if (e >= E) return;
    int u = ei[e];
    int v = ei[E + e];
    if (u == v) return;                         // diagonal is zeroed in ref
    atomicOr(&g_bits[(size_t)u * WORDS + (v >> 6)], 1ull << (v & 63));
}

__global__ void node_stats_kernel(const float* __restrict__ x) {
    int node = blockIdx.x * 8 + (threadIdx.x >> 5);
    int lane = threadIdx.x & 31;
    const unsigned long long* row = g_bits + (size_t)node * WORDS;
    int cnt = 0;
#pragma unroll
    for (int i = 0; i < 4; i++) cnt += __popcll(row[i * 32 + lane]);
    // squared norm: 128 floats = 32 float4, one per lane
    float4 a = ((const float4*)(x + (size_t)node * INCH))[lane];
    float nrm = a.x * a.x + a.y * a.y + a.z * a.z + a.w * a.w;
#pragma unroll
    for (int o = 16; o; o >>= 1) {
        cnt += __shfl_xor_sync(0xffffffffu, cnt, o);
        nrm += __shfl_xor_sync(0xffffffffu, nrm, o);
    }
    if (lane == 0) {
        float deg = (float)cnt;
        g_norm[node]   = sqrtf(nrm);
        g_invlog[node] = (cnt > 1) ? (1.0f / logf(deg)) : 0.0f;
        g_invdeg[node] = (cnt > 0) ? (1.0f / deg) : 0.0f;
    }
}

__global__ void combine_w_kernel(const float* __restrict__ W1) {
    int i = blockIdx.x * 256 + threadIdx.x;     // 0 .. 128*256-1
    float we = W1[512 * HID + i];               // xu+xv block
    g_Wa[i] = W1[i] + we;                       // xu block + (xu+xv)
    g_Wb[i] = W1[128 * HID + i] + we;           // xv block + (xu+xv)
}

// pre_u / pre_v GEMM: M=8192, N=256, K=128. blockIdx.y selects Wa/Wb.
__global__ __launch_bounds__(256) void pre_gemm_kernel(const float* __restrict__ x) {
    __shared__ float As[32 * 128];              // 16 KB
    __shared__ float Bs[16 * 256];              // 16 KB
    const float* B = blockIdx.y ? g_Wb : g_Wa;
    float* out = blockIdx.y ? g_prev : g_preu;
    int t = threadIdx.x;
    int m0 = blockIdx.x * 32;
    // load A tile (32 x 128 = 1024 float4)
    {
        const float4* xg = (const float4*)(x + (size_t)m0 * INCH);
        float4* A4 = (float4*)As;
#pragma unroll
        for (int i = 0; i < 4; i++) A4[t + i * 256] = xg[t + i * 256];
    }
    int ty = t >> 5, tx = t & 31;               // rows ty*4.., cols tx*8..
    float acc[4][8];
#pragma unroll
    for (int i = 0; i < 4; i++)
#pragma unroll
        for (int j = 0; j < 8; j++) acc[i][j] = 0.0f;

    for (int kt = 0; kt < 8; kt++) {
        __syncthreads();
        const float4* Bg = (const float4*)(B + kt * 16 * HID);
        float4* B4 = (float4*)Bs;
#pragma unroll
        for (int i = 0; i < 4; i++) B4[t + i * 256] = Bg[t + i * 256];
        __syncthreads();
#pragma unroll
        for (int kk = 0; kk < 16; kk++) {
            int k = kt * 16 + kk;
            float a[4];
#pragma unroll
            for (int i = 0; i < 4; i++) a[i] = As[(ty * 4 + i) * 128 + k];
            float4 b0 = *(const float4*)&Bs[kk * 256 + tx * 8];
            float4 b1 = *(const float4*)&Bs[kk * 256 + tx * 8 + 4];
            float bb[8] = {b0.x, b0.y, b0.z, b0.w, b1.x, b1.y, b1.z, b1.w};
#pragma unroll
            for (int i = 0; i < 4; i++)
#pragma unroll
                for (int j = 0; j < 8; j++) acc[i][j] = fmaf(a[i], bb[j], acc[i][j]);
        }
    }
#pragma unroll
    for (int i = 0; i < 4; i++) {
        float* o = out + (size_t)(m0 + ty * 4 + i) * HID + tx * 8;
#pragma unroll
        for (int j = 0; j < 8; j++) o[j] = acc[i][j];
    }
}

// --------------------------- main pair kernel ------------------------------
// Dyn smem layout (floats):
//   A_s   [16640]   GEMM1 A [k:256][m:64]  then  h1 [m:64][pad:260]
//   B_s   [8256]    GEMM tiles (32x256 / 32x128)  then  h2 [m:64][pad:129]
//   Wex   [1024]    W1 rows 640..643 (cos, cn, aa, ra)
//   b1s[256] b2s[128] W3s[128] dotp[256] sc[256]  us/vs[64+64 ints]
#define OFF_A     0
#define OFF_B     16640
#define OFF_WEX   (16640 + 8256)
#define OFF_B1    (OFF_WEX + 1024)
#define OFF_B2    (OFF_B1 + 256)
#define OFF_W3    (OFF_B2 + 128)
#define OFF_DOT   (OFF_W3 + 128)
#define OFF_SC    (OFF_DOT + 256)
#define OFF_UV    (OFF_SC + 256)
#define SMEM_FLOATS (OFF_UV + 128)
#define SMEM_BYTES  (SMEM_FLOATS * 4)   // 108288 B -> 2 CTAs/SM

__global__ __launch_bounds__(256, 2) void pair_kernel(
    const float* __restrict__ x,
    const int* __restrict__ pairs,
    const float* __restrict__ W1,
    const float* __restrict__ b1,
    const float* __restrict__ W2,
    const float* __restrict__ b2,
    const float* __restrict__ W3,
    const float* __restrict__ b3,
    float* __restrict__ out) {
    extern __shared__ float smem[];
    float* A_s  = smem + OFF_A;
    float* B_s  = smem + OFF_B;
    float* Wex  = smem + OFF_WEX;
    float* b1s  = smem + OFF_B1;
    float* b2s  = smem + OFF_B2;
    float* W3s  = smem + OFF_W3;
    float* dotp = smem + OFF_DOT;
    float* sc   = smem + OFF_SC;          // [0:64)=cos [64:128)=cn [128:192)=aa [192:256)=ra
    int*   us   = (int*)(smem + OFF_UV);
    int*   vs   = us + 64;

    int t = threadIdx.x;
    int pair0 = blockIdx.x * TBP;

    if (t < TBP) {
        us[t] = pairs[2 * (pair0 + t)];
        vs[t] = pairs[2 * (pair0 + t) + 1];
    }
    for (int i = t; i < 1024; i += 256) Wex[i] = W1[640 * HID + i];
    b1s[t] = b1[t];
    if (t < 128) { b2s[t] = b2[t]; W3s[t] = W3[t]; }
    __syncthreads();

    // ---- Phase A: pairwise features p=xu*xv, q=|xu-xv| into A_s[k][m] ----
    {
        int m = t & 63, s = t >> 6;       // 4 threads per pair, 32 feats each
        int u = us[m], v = vs[m];
        const float4* xu = (const float4*)(x + (size_t)u * INCH + s * 32);
        const float4* xv = (const float4*)(x + (size_t)v * INCH + s * 32);
        float dot = 0.0f;
#pragma unroll
        for (int i = 0; i < 8; i++) {
            float4 a = xu[i], b = xv[i];
            int f = s * 32 + i * 4;
            float p0 = a.x * b.x, p1 = a.y * b.y, p2 = a.z * b.z, p3 = a.w * b.w;
            dot += p0 + p1 + p2 + p3;
            A_s[(f + 0) * 64 + m] = p0;
            A_s[(f + 1) * 64 + m] = p1;
            A_s[(f + 2) * 64 + m] = p2;
            A_s[(f + 3) * 64 + m] = p3;
            A_s[(128 + f + 0) * 64 + m] = fabsf(a.x - b.x);
            A_s[(128 + f + 1) * 64 + m] = fabsf(a.y - b.y);
            A_s[(128 + f + 2) * 64 + m] = fabsf(a.z - b.z);
            A_s[(128 + f + 3) * 64 + m] = fabsf(a.w - b.w);
        }
        dotp[s * 64 + m] = dot;
    }
    __syncthreads();

    // ---- cosine (64 threads) ----
    if (t < TBP) {
        float d = dotp[t] + dotp[64 + t] + dotp[128 + t] + dotp[192 + t];
        float nn = g_norm[us[t]] * g_norm[vs[t]];
        sc[t] = d / fmaxf(nn, EPSF);
    }

    // ---- Phase B: common-neighbor stats via bitsets (warp per 8 pairs) ----
    {
        int w = t >> 5, lane = t & 31;
        for (int pp = 0; pp < 8; pp++) {
            int m = w * 8 + pp;
            const unsigned long long* bu = g_bits + (size_t)us[m] * WORDS;
            const unsigned long long* bv = g_bits + (size_t)vs[m] * WORDS;
            int cn = 0; float aa = 0.0f, ra = 0.0f;
#pragma unroll
            for (int it = 0; it < 4; it++) {
                int wi = it * 32 + lane;
                unsigned long long c = bu[wi] & bv[wi];
                cn += __popcll(c);
                while (c) {
                    int b = __ffsll((long long)c) - 1;
                    c &= c - 1;
                    int idx = wi * 64 + b;
                    aa += g_invlog[idx];
                    ra += g_invdeg[idx];
                }
            }
#pragma unroll
            for (int o = 16; o; o >>= 1) {
                cn += __shfl_xor_sync(0xffffffffu, cn, o);
                aa += __shfl_xor_sync(0xffffffffu, aa, o);
                ra += __shfl_xor_sync(0xffffffffu, ra, o);
            }
            if (lane == 0) { sc[64 + m] = (float)cn; sc[128 + m] = aa; sc[192 + m] = ra; }
        }
    }
    __syncthreads();

    // ---- GEMM1: h1[64x256] = [p;q] @ W1[256:512]  (f32x2 packed on N) ----
    int ty = t >> 5, tx = t & 31;         // M rows ty*8.., N cols tx*8..
    const float* Bg = W1 + 256 * HID;     // rows 256..511, contiguous
    unsigned long long acc[8][4];
#pragma unroll
    for (int i = 0; i < 8; i++)
#pragma unroll
        for (int j = 0; j < 4; j++) acc[i][j] = 0ull;

    for (int kt = 0; kt < 8; kt++) {
        __syncthreads();
        const float4* Bg4 = (const float4*)(Bg + kt * 32 * HID);
        float4* B4 = (float4*)B_s;
#pragma unroll
        for (int i = 0; i < 8; i++) B4[t + i * 256] = Bg4[t + i * 256];
        __syncthreads();
#pragma unroll 8
        for (int kk = 0; kk < 32; kk++) {
            const float* ap = &A_s[(kt * 32 + kk) * 64 + ty * 8];
            float4 a0 = *(const float4*)ap;
            float4 a1 = *(const float4*)(ap + 4);
            unsigned long long ad[8];
            ad[0] = pk2(a0.x); ad[1] = pk2(a0.y); ad[2] = pk2(a0.z); ad[3] = pk2(a0.w);
            ad[4] = pk2(a1.x); ad[5] = pk2(a1.y); ad[6] = pk2(a1.z); ad[7] = pk2(a1.w);
            const ulonglong2* bp = (const ulonglong2*)&B_s[kk * 256 + tx * 8];
            ulonglong2 bA = bp[0], bB = bp[1];
#pragma unroll
            for (int i = 0; i < 8; i++) {
                acc[i][0] = fma2(ad[i], bA.x, acc[i][0]);
                acc[i][1] = fma2(ad[i], bA.y, acc[i][1]);
                acc[i][2] = fma2(ad[i], bB.x, acc[i][2]);
                acc[i][3] = fma2(ad[i], bB.y, acc[i][3]);
            }
        }
    }
    __syncthreads();

    // ---- Epilogue1: + pre_u + pre_v + b1 + scalar feats, relu -> A_s[m][260]
#pragma unroll
    for (int i = 0; i < 8; i++) {
        int m = ty * 8 + i;
        int u = us[m], v = vs[m];
        float cosm = sc[m], cnm = sc[64 + m], aam = sc[128 + m], ram = sc[192 + m];
        int n0 = tx * 8;
        const float* pu = g_preu + (size_t)u * HID + n0;
        const float* pv = g_prev + (size_t)v * HID + n0;
        float vals[8];
        vals[0] = lo2(acc[i][0]); vals[1] = hi2(acc[i][0]);
        vals[2] = lo2(acc[i][1]); vals[3] = hi2(acc[i][1]);
        vals[4] = lo2(acc[i][2]); vals[5] = hi2(acc[i][2]);
        vals[6] = lo2(acc[i][3]); vals[7] = hi2(acc[i][3]);
#pragma unroll
        for (int j = 0; j < 8; j++) {
            int n = n0 + j;
            float h = vals[j] + pu[j] + pv[j] + b1s[n];
            h = fmaf(cosm, Wex[n], h);
            h = fmaf(cnm,  Wex[256 + n], h);
            h = fmaf(aam,  Wex[512 + n], h);
            h = fmaf(ram,  Wex[768 + n], h);
            A_s[m * 260 + n] = fmaxf(h, 0.0f);
        }
    }
    __syncthreads();

    // ---- GEMM2: h2[64x128] = h1 @ W2(256x128) ----
    unsigned long long acc2[8][2];
#pragma unroll
    for (int i = 0; i < 8; i++) { acc2[i][0] = 0ull; acc2[i][1] = 0ull; }

    for (int kt = 0; kt < 8; kt++) {
        __syncthreads();
        const float4* W2g4 = (const float4*)(W2 + kt * 32 * HID2);
        float4* B4 = (float4*)B_s;
#pragma unroll
        for (int i = 0; i < 4; i++) B4[t + i * 256] = W2g4[t + i * 256];
        __syncthreads();
#pragma unroll 8
        for (int kk = 0; kk < 32; kk++) {
            int k = kt * 32 + kk;
            ulonglong2 bq = *(const ulonglong2*)&B_s[kk * 128 + tx * 4];
#pragma unroll
            for (int i = 0; i < 8; i++) {
                unsigned long long ai = pk2(A_s[(ty * 8 + i) * 260 + k]);
                acc2[i][0] = fma2(ai, bq.x, acc2[i][0]);
                acc2[i][1] = fma2(ai, bq.y, acc2[i][1]);
            }
        }
    }
    __syncthreads();

    // ---- Epilogue2: relu(h2+b2) -> B_s[m][129] ----
#pragma unroll
    for (int i = 0; i < 8; i++) {
        int m = ty * 8 + i;
        int n = tx * 4;
        B_s[m * 129 + n + 0] = fmaxf(lo2(acc2[i][0]) + b2s[n + 0], 0.0f);
        B_s[m * 129 + n + 1] = fmaxf(hi2(acc2[i][0]) + b2s[n + 1], 0.0f);
        B_s[m * 129 + n + 2] = fmaxf(lo2(acc2[i][1]) + b2s[n + 2], 0.0f);
        B_s[m * 129 + n + 3] = fmaxf(hi2(acc2[i][1]) + b2s[n + 3], 0.0f);
    }
    __syncthreads();

    // ---- GEMV: s = h2 @ W3 + b3 ----
    if (t < TBP) {
        const float* h = &B_s[t * 129];
        float s0 = 0.0f, s1 = 0.0f;
#pragma unroll
        for (int j = 0; j < 128; j += 2) {
            s0 = fmaf(h[j], W3s[j], s0);
            s1 = fmaf(h[j + 1], W3s[j + 1], s1);
        }
        out[pair0 + t] = s0 + s1 + b3[0];
    }
}

// --------------------------- launcher --------------------------------------
extern "C" void kernel_launch(void* const* d_in, const int* in_sizes, int n_in,
                              void* d_out, int out_size) {
    const float* x  = (const float*)d_in[0];
    const int* ei   = (const int*)d_in[1];
    const int* ep   = (const int*)d_in[2];
    const float* W1 = (const float*)d_in[3];
    const float* b1 = (const float*)d_in[4];
    const float* W2 = (const float*)d_in[5];
    const float* b2 = (const float*)d_in[6];
    const float* W3 = (const float*)d_in[7];
    const float* b3 = (const float*)d_in[8];
    float* out      = (float*)d_out;

    int E = in_sizes[1] / 2;     // 262144
    int P = in_sizes[2] / 2;     // 65536

    // bits are idempotent (atomicOr of identical edges) -> no clear needed,
    // deterministic across graph replays.
    build_bits_kernel<<<(E + 255) / 256, 256>>>(ei, E);
    node_stats_kernel<<<NNODES / 8, 256>>>(x);
    combine_w_kernel<<<128, 256>>>(W1);
    pre_gemm_kernel<<<dim3(NNODES / 32, 2), 256>>>(x);

    cudaFuncSetAttribute(pair_kernel,
                         cudaFuncAttributeMaxDynamicSharedMemorySize, SMEM_BYTES);
    pair_kernel<<<P / TBP, 256, SMEM_BYTES>>>(x, ep, W1, b1, W2, b2, W3, b3, out);
}

// round 11
// speedup vs baseline: 1.6741x; 1.6741x over previous
#include <cuda_runtime.h>
#include <cuda_bf16.h>
#include <cstdint>
#include <math.h>

// ---------------------------------------------------------------------------
// PairwiseMLPLinkPredictor — GB300 sm_103a (toolchain targets sm_103 base,
// so no tcgen05; tensor pipe used via mma.sync bf16 HMMA).
//
// GEMM1/GEMM2: fp32 operands split into bf16 hi+lo, compensated:
//   D = Ah*Bh + Ah*Bl + Al*Bh   (fp32 accum, rel err ~1e-5)
// ---------------------------------------------------------------------------

#define NNODES   8192
#define WORDS    128
#define INCH     128
#define HID      256
#define HID2     128
#define TBP      64           // pairs per CTA
#define EPSF     1e-8f

// --------------------------- device scratch --------------------------------
__device__ unsigned long long g_bits[(size_t)NNODES * WORDS];   // 8 MB
__device__ float g_invlog[NNODES];
__device__ float g_invdeg[NNODES];
__device__ float g_norm[NNODES];
__device__ float g_Wa[INCH * HID];
__device__ float g_Wb[INCH * HID];
__device__ float g_preu[(size_t)NNODES * HID];                  // 8 MB
__device__ float g_prev[(size_t)NNODES * HID];                  // 8 MB
// Pre-split bf16 weights, plain [n][k] row-major, k contiguous.
__device__ unsigned short g_B1hi[256 * 256];   // W1 rows 256:512 transposed
__device__ unsigned short g_B1lo[256 * 256];
__device__ unsigned short g_B2hi[128 * 256];   // W2^T
__device__ unsigned short g_B2lo[128 * 256];

// --------------------------- helpers ---------------------------------------
__device__ __forceinline__ uint32_t smem_u32(const void* p) {
    uint32_t a;
    asm("{ .reg .u64 t; cvta.to.shared.u64 t, %1; cvt.u32.u64 %0, t; }"
        : "=r"(a) : "l"(p));
    return a;
}

#define LDSM_X4(r, addr) \
    asm volatile("ldmatrix.sync.aligned.m8n8.x4.shared.b16 {%0,%1,%2,%3}, [%4];" \
        : "=r"((r)[0]), "=r"((r)[1]), "=r"((r)[2]), "=r"((r)[3]) : "r"(addr))

#define MMA16816(c, a, b0, b1) \
    asm volatile("mma.sync.aligned.m16n8k16.row.col.f32.bf16.bf16.f32 " \
        "{%0,%1,%2,%3}, {%4,%5,%6,%7}, {%8,%9}, {%0,%1,%2,%3};" \
        : "+f"((c)[0]), "+f"((c)[1]), "+f"((c)[2]), "+f"((c)[3]) \
        : "r"((a)[0]), "r"((a)[1]), "r"((a)[2]), "r"((a)[3]), "r"(b0), "r"(b1))

__device__ __forceinline__ void bsplit(float v, unsigned short& h, unsigned short& l) {
    __nv_bfloat16 hb = __float2bfloat16(v);
    __nv_bfloat16 lb = __float2bfloat16(v - __bfloat162float(hb));
    h = *reinterpret_cast<unsigned short*>(&hb);
    l = *reinterpret_cast<unsigned short*>(&lb);
}
// pack 2 bf16 into u32
__device__ __forceinline__ uint32_t pack2(unsigned short a, unsigned short b) {
    return (uint32_t)a | ((uint32_t)b << 16);
}

// --------------------------- prep kernels ----------------------------------
__global__ void build_bits_kernel(const int* __restrict__ ei, int E) {
    int e = blockIdx.x * blockDim.x + threadIdx.x;
    if (e >= E) return;
    int u = ei[e];
    int v = ei[E + e];
    if (u == v) return;
    atomicOr(&g_bits[(size_t)u * WORDS + (v >> 6)], 1ull << (v & 63));
}

__global__ void node_stats_kernel(const float* __restrict__ x) {
    int node = blockIdx.x * 8 + (threadIdx.x >> 5);
    int lane = threadIdx.x & 31;
    const unsigned long long* row = g_bits + (size_t)node * WORDS;
    int cnt = 0;
#pragma unroll
    for (int i = 0; i < 4; i++) cnt += __popcll(row[i * 32 + lane]);
    float4 a = ((const float4*)(x + (size_t)node * INCH))[lane];
    float nrm = a.x * a.x + a.y * a.y + a.z * a.z + a.w * a.w;
#pragma unroll
    for (int o = 16; o; o >>= 1) {
        cnt += __shfl_xor_sync(0xffffffffu, cnt, o);
        nrm += __shfl_xor_sync(0xffffffffu, nrm, o);
    }
    if (lane == 0) {
        float deg = (float)cnt;
        g_norm[node]   = sqrtf(nrm);
        g_invlog[node] = (cnt > 1) ? (1.0f / logf(deg)) : 0.0f;
        g_invdeg[node] = (cnt > 0) ? (1.0f / deg) : 0.0f;
    }
}

__global__ void combine_w_kernel(const float* __restrict__ W1) {
    int i = blockIdx.x * 256 + threadIdx.x;
    float we = W1[512 * HID + i];
    g_Wa[i] = W1[i] + we;
    g_Wb[i] = W1[128 * HID + i] + we;
}

// Split + transpose W1 rows 256:512 -> g_B1 [n=256][k=256]; W2 -> g_B2 [n=128][k=256]
__global__ void w_split_kernel(const float* __restrict__ W1,
                               const float* __restrict__ W2) {
    int idx = blockIdx.x * 256 + threadIdx.x;
    if (idx < 65536) {
        int n = idx >> 8, k = idx & 255;
        float v = W1[(size_t)(256 + k) * HID + n];
        unsigned short h, l; bsplit(v, h, l);
        g_B1hi[n * 256 + k] = h;
        g_B1lo[n * 256 + k] = l;
    } else if (idx < 98304) {
        int j = idx - 65536;
        int n = j >> 8, k = j & 255;
        float v = W2[(size_t)k * HID2 + n];
        unsigned short h, l; bsplit(v, h, l);
        g_B2hi[n * 256 + k] = h;
        g_B2lo[n * 256 + k] = l;
    }
}

// pre_u / pre_v GEMM (unchanged from passing version)
__global__ __launch_bounds__(256) void pre_gemm_kernel(const float* __restrict__ x) {
    __shared__ float As[32 * 128];
    __shared__ float Bs[16 * 256];
    const float* B = blockIdx.y ? g_Wb : g_Wa;
    float* out = blockIdx.y ? g_prev : g_preu;
    int t = threadIdx.x;
    int m0 = blockIdx.x * 32;
    {
        const float4* xg = (const float4*)(x + (size_t)m0 * INCH);
        float4* A4 = (float4*)As;
#pragma unroll
        for (int i = 0; i < 4; i++) A4[t + i * 256] = xg[t + i * 256];
    }
    int ty = t >> 5, tx = t & 31;
    float acc[4][8];
#pragma unroll
    for (int i = 0; i < 4; i++)
#pragma unroll
        for (int j = 0; j < 8; j++) acc[i][j] = 0.0f;

    for (int kt = 0; kt < 8; kt++) {
        __syncthreads();
        const float4* Bg = (const float4*)(B + kt * 16 * HID);
        float4* B4 = (float4*)Bs;
#pragma unroll
        for (int i = 0; i < 4; i++) B4[t + i * 256] = Bg[t + i * 256];
        __syncthreads();
#pragma unroll
        for (int kk = 0; kk < 16; kk++) {
            int k = kt * 16 + kk;
            float a[4];
#pragma unroll
            for (int i = 0; i < 4; i++) a[i] = As[(ty * 4 + i) * 128 + k];
            float4 b0 = *(const float4*)&Bs[kk * 256 + tx * 8];
            float4 b1 = *(const float4*)&Bs[kk * 256 + tx * 8 + 4];
            float bb[8] = {b0.x, b0.y, b0.z, b0.w, b1.x, b1.y, b1.z, b1.w};
#pragma unroll
            for (int i = 0; i < 4; i++)
#pragma unroll
                for (int j = 0; j < 8; j++) acc[i][j] = fmaf(a[i], bb[j], acc[i][j]);
        }
    }
#pragma unroll
    for (int i = 0; i < 4; i++) {
        float* o = out + (size_t)(m0 + ty * 4 + i) * HID + tx * 8;
#pragma unroll
        for (int j = 0; j < 8; j++) o[j] = acc[i][j];
    }
}

// --------------------------- main pair kernel (mma.sync) -------------------
// A buffers: 64 rows x 264 bf16 (528 B/row, pad -> conflict-free ldmatrix)
// B buffers: 256 rows x 72 bf16 (144 B/row)
#define A_STRIDE 528
#define B_STRIDE 144
#define OFF_A1HI 0                    // 33792
#define OFF_A1LO 33792                // 33792
#define OFF_BHI  67584                // 36864
#define OFF_BLO  104448               // 36864 -> 141312
#define OFF_US   141312               // 256
#define OFF_VS   141568               // 256
#define OFF_DOT  141824               // 1024
#define OFF_SCC  142848               // 256
#define OFF_SCN  143104
#define OFF_SCA  143360
#define OFF_SCR  143616
#define OFF_WEX  143872               // 4096
#define OFF_B1S  147968               // 1024
#define OFF_B2S  148992               // 512
#define OFF_W3S  149504               // 512
#define OFF_SRED 150016               // 512
#define SMEM2    150528

__global__ __launch_bounds__(256, 1) void pair3_kernel(
    const float* __restrict__ x,
    const int* __restrict__ pairs,
    const float* __restrict__ W1,
    const float* __restrict__ b1,
    const float* __restrict__ b2,
    const float* __restrict__ W3,
    const float* __restrict__ b3,
    float* __restrict__ out) {
    extern __shared__ char sm[];
    uint32_t smu = smem_u32(sm);
    char*  A1hi = sm + OFF_A1HI;
    char*  A1lo = sm + OFF_A1LO;
    int*   us   = (int*)(sm + OFF_US);
    int*   vs   = (int*)(sm + OFF_VS);
    float* dotp = (float*)(sm + OFF_DOT);
    float* scC  = (float*)(sm + OFF_SCC);
    float* scN  = (float*)(sm + OFF_SCN);
    float* scA  = (float*)(sm + OFF_SCA);
    float* scR  = (float*)(sm + OFF_SCR);
    float* Wex  = (float*)(sm + OFF_WEX);
    float* b1s  = (float*)(sm + OFF_B1S);
    float* b2s  = (float*)(sm + OFF_B2S);
    float* W3s  = (float*)(sm + OFF_W3S);
    float* sred = (float*)(sm + OFF_SRED);

    int t = threadIdx.x;
    int wid = t >> 5, lane = t & 31;
    int g = lane >> 2, tq = lane & 3;
    int pair0 = blockIdx.x * TBP;

    if (t < TBP) {
        us[t] = pairs[2 * (pair0 + t)];
        vs[t] = pairs[2 * (pair0 + t) + 1];
    }
    for (int i = t; i < 1024; i += 256) Wex[i] = W1[640 * HID + i];
    b1s[t] = b1[t];
    if (t < 128) { b2s[t] = b2[t]; W3s[t] = W3[t]; }
    __syncthreads();

    // ---- Phase A: features -> A1 hi/lo row-major bf16 ---------------------
    {
        int m = t & 63, s = t >> 6;            // 4 threads/pair, dims s*32..
        const float4* xu4 = (const float4*)(x + (size_t)us[m] * INCH + s * 32);
        const float4* xv4 = (const float4*)(x + (size_t)vs[m] * INCH + s * 32);
        unsigned short* Ah = (unsigned short*)(A1hi + m * A_STRIDE);
        unsigned short* Al = (unsigned short*)(A1lo + m * A_STRIDE);
        float dot = 0.0f;
#pragma unroll
        for (int i = 0; i < 8; i++) {
            float4 a = xu4[i], b = xv4[i];
            int f = s * 32 + i * 4;
            float p0 = a.x * b.x, p1 = a.y * b.y, p2 = a.z * b.z, p3 = a.w * b.w;
            dot += p0 + p1 + p2 + p3;
            unsigned short h0,l0,h1,l1,h2,l2,h3,l3;
            bsplit(p0,h0,l0); bsplit(p1,h1,l1); bsplit(p2,h2,l2); bsplit(p3,h3,l3);
            *(uint2*)(Ah + f)       = make_uint2(pack2(h0,h1), pack2(h2,h3));
            *(uint2*)(Al + f)       = make_uint2(pack2(l0,l1), pack2(l2,l3));
            float q0 = fabsf(a.x-b.x), q1 = fabsf(a.y-b.y), q2 = fabsf(a.z-b.z), q3 = fabsf(a.w-b.w);
            bsplit(q0,h0,l0); bsplit(q1,h1,l1); bsplit(q2,h2,l2); bsplit(q3,h3,l3);
            *(uint2*)(Ah + 128 + f) = make_uint2(pack2(h0,h1), pack2(h2,h3));
            *(uint2*)(Al + 128 + f) = make_uint2(pack2(l0,l1), pack2(l2,l3));
        }
        dotp[s * 64 + m] = dot;
    }
    __syncthreads();
    if (t < TBP) {
        float d = dotp[t] + dotp[64 + t] + dotp[128 + t] + dotp[192 + t];
        float nn = g_norm[us[t]] * g_norm[vs[t]];
        scC[t] = d / fmaxf(nn, EPSF);
    }

    // ---- Phase B: common-neighbor stats (warp per 8 pairs) ----------------
    {
        for (int pp = 0; pp < 8; pp++) {
            int m = wid * 8 + pp;
            const unsigned long long* bu = g_bits + (size_t)us[m] * WORDS;
            const unsigned long long* bv = g_bits + (size_t)vs[m] * WORDS;
            int cn = 0; float aa = 0.0f, ra = 0.0f;
#pragma unroll
            for (int it = 0; it < 4; it++) {
                int wi = it * 32 + lane;
                unsigned long long c = bu[wi] & bv[wi];
                cn += __popcll(c);
                while (c) {
                    int b = __ffsll((long long)c) - 1;
                    c &= c - 1;
                    int idx = wi * 64 + b;
                    aa += g_invlog[idx];
                    ra += g_invdeg[idx];
                }
            }
#pragma unroll
            for (int o = 16; o; o >>= 1) {
                cn += __shfl_xor_sync(0xffffffffu, cn, o);
                aa += __shfl_xor_sync(0xffffffffu, aa, o);
                ra += __shfl_xor_sync(0xffffffffu, ra, o);
            }
            if (lane == 0) { scN[m] = (float)cn; scA[m] = aa; scR[m] = ra; }
        }
    }

    // ---- GEMM1: h1[64x256] via mma.sync, K chunks of 64 -------------------
    int m0 = (wid & 3) * 16;
    int n0 = (wid >> 2) * 128;
    float acc1[16][4];
#pragma unroll
    for (int i = 0; i < 16; i++)
#pragma unroll
        for (int j = 0; j < 4; j++) acc1[i][j] = 0.0f;

    // A-fragment smem addresses (row = m0 + lane&15, col-half by lane>>4)
    uint32_t aAh = smu + OFF_A1HI + (m0 + (lane & 15)) * A_STRIDE + ((lane >> 4) & 1) * 16;
    uint32_t aAl = aAh + (OFF_A1LO - OFF_A1HI);
    // B-fragment base: row = n0 + g*16 + (lane&7) + ((lane>>4)&1)*8 ; colhalf by lane>>3
    uint32_t bRow = (lane & 7) + ((lane >> 4) & 1) * 8;
    uint32_t bColH = ((lane >> 3) & 1) * 16;

    for (int kc = 0; kc < 4; kc++) {
        __syncthreads();
        for (int i = t; i < 2048; i += 256) {
            int n = i >> 3, q = i & 7;
            ((uint4*)(sm + OFF_BHI))[n * 9 + q] = ((const uint4*)g_B1hi)[n * 32 + kc * 8 + q];
            ((uint4*)(sm + OFF_BLO))[n * 9 + q] = ((const uint4*)g_B1lo)[n * 32 + kc * 8 + q];
        }
        __syncthreads();
#pragma unroll
        for (int ks = 0; ks < 4; ks++) {
            uint32_t kb = (kc * 64 + ks * 16) * 2;
            uint32_t ah[4], al[4];
            LDSM_X4(ah, aAh + kb);
            LDSM_X4(al, aAl + kb);
#pragma unroll
            for (int gp = 0; gp < 8; gp++) {
                uint32_t baddr = smu + OFF_BHI + (n0 + gp * 16 + bRow) * B_STRIDE + ks * 32 + bColH;
                uint32_t bh[4], bl[4];
                LDSM_X4(bh, baddr);
                LDSM_X4(bl, baddr + (OFF_BLO - OFF_BHI));
                MMA16816(acc1[gp * 2],     ah, bh[0], bh[1]);
                MMA16816(acc1[gp * 2],     ah, bl[0], bl[1]);
                MMA16816(acc1[gp * 2],     al, bh[0], bh[1]);
                MMA16816(acc1[gp * 2 + 1], ah, bh[2], bh[3]);
                MMA16816(acc1[gp * 2 + 1], ah, bl[2], bl[3]);
                MMA16816(acc1[gp * 2 + 1], al, bh[2], bh[3]);
            }
        }
    }
    __syncthreads();                     // stats done too (Phase B any warp)

    // ---- Epilogue1: h1 = relu(D1 + pre_u + pre_v + b1 + scalars) -> A1 ----
    {
        int r0 = m0 + g, r1 = r0 + 8;
        int u0 = us[r0], v0 = vs[r0], u1 = us[r1], v1 = vs[r1];
        float c0m = scC[r0], n0m = scN[r0], a0m = scA[r0], q0m = scR[r0];
        float c1m = scC[r1], n1m = scN[r1], a1m = scA[r1], q1m = scR[r1];
        unsigned short* Ah0 = (unsigned short*)(A1hi + r0 * A_STRIDE);
        unsigned short* Al0 = (unsigned short*)(A1lo + r0 * A_STRIDE);
        unsigned short* Ah1 = (unsigned short*)(A1hi + r1 * A_STRIDE);
        unsigned short* Al1 = (unsigned short*)(A1lo + r1 * A_STRIDE);
#pragma unroll
        for (int nt = 0; nt < 16; nt++) {
            int n = n0 + nt * 8 + tq * 2;
            float2 pu0 = *(const float2*)(g_preu + (size_t)u0 * HID + n);
            float2 pv0 = *(const float2*)(g_prev + (size_t)v0 * HID + n);
            float2 pu1 = *(const float2*)(g_preu + (size_t)u1 * HID + n);
            float2 pv1 = *(const float2*)(g_prev + (size_t)v1 * HID + n);
            float w0a = Wex[n], w0b = Wex[n + 1];
            float w1a = Wex[256 + n], w1b = Wex[256 + n + 1];
            float w2a = Wex[512 + n], w2b = Wex[512 + n + 1];
            float w3a = Wex[768 + n], w3b = Wex[768 + n + 1];
            float ba = b1s[n], bb = b1s[n + 1];
            float h00 = acc1[nt][0] + pu0.x + pv0.x + ba;
            h00 = fmaf(c0m, w0a, h00); h00 = fmaf(n0m, w1a, h00);
            h00 = fmaf(a0m, w2a, h00); h00 = fmaf(q0m, w3a, h00);
            float h01 = acc1[nt][1] + pu0.y + pv0.y + bb;
            h01 = fmaf(c0m, w0b, h01); h01 = fmaf(n0m, w1b, h01);
            h01 = fmaf(a0m, w2b, h01); h01 = fmaf(q0m, w3b, h01);
            float h10 = acc1[nt][2] + pu1.x + pv1.x + ba;
            h10 = fmaf(c1m, w0a, h10); h10 = fmaf(n1m, w1a, h10);
            h10 = fmaf(a1m, w2a, h10); h10 = fmaf(q1m, w3a, h10);
            float h11 = acc1[nt][3] + pu1.y + pv1.y + bb;
            h11 = fmaf(c1m, w0b, h11); h11 = fmaf(n1m, w1b, h11);
            h11 = fmaf(a1m, w2b, h11); h11 = fmaf(q1m, w3b, h11);
            h00 = fmaxf(h00, 0.0f); h01 = fmaxf(h01, 0.0f);
            h10 = fmaxf(h10, 0.0f); h11 = fmaxf(h11, 0.0f);
            unsigned short hh0, ll0, hh1, ll1;
            bsplit(h00, hh0, ll0); bsplit(h01, hh1, ll1);
            *(uint32_t*)(Ah0 + n) = pack2(hh0, hh1);
            *(uint32_t*)(Al0 + n) = pack2(ll0, ll1);
            bsplit(h10, hh0, ll0); bsplit(h11, hh1, ll1);
            *(uint32_t*)(Ah1 + n) = pack2(hh0, hh1);
            *(uint32_t*)(Al1 + n) = pack2(ll0, ll1);
        }
    }

    // ---- GEMM2: h2[64x128] = h1 @ W2 --------------------------------------
    int n02 = (wid >> 2) * 64;
    float acc2[8][4];
#pragma unroll
    for (int i = 0; i < 8; i++)
#pragma unroll
        for (int j = 0; j < 4; j++) acc2[i][j] = 0.0f;

    for (int kc = 0; kc < 4; kc++) {
        __syncthreads();
        for (int i = t; i < 1024; i += 256) {
            int n = i >> 3, q = i & 7;
            ((uint4*)(sm + OFF_BHI))[n * 9 + q] = ((const uint4*)g_B2hi)[n * 32 + kc * 8 + q];
            ((uint4*)(sm + OFF_BLO))[n * 9 + q] = ((const uint4*)g_B2lo)[n * 32 + kc * 8 + q];
        }
        __syncthreads();
#pragma unroll
        for (int ks = 0; ks < 4; ks++) {
            uint32_t kb = (kc * 64 + ks * 16) * 2;
            uint32_t ah[4], al[4];
            LDSM_X4(ah, aAh + kb);
            LDSM_X4(al, aAl + kb);
#pragma unroll
            for (int gp = 0; gp < 4; gp++) {
                uint32_t baddr = smu + OFF_BHI + (n02 + gp * 16 + bRow) * B_STRIDE + ks * 32 + bColH;
                uint32_t bh[4], bl[4];
                LDSM_X4(bh, baddr);
                LDSM_X4(bl, baddr + (OFF_BLO - OFF_BHI));
                MMA16816(acc2[gp * 2],     ah, bh[0], bh[1]);
                MMA16816(acc2[gp * 2],     ah, bl[0], bl[1]);
                MMA16816(acc2[gp * 2],     al, bh[0], bh[1]);
                MMA16816(acc2[gp * 2 + 1], ah, bh[2], bh[3]);
                MMA16816(acc2[gp * 2 + 1], ah, bl[2], bl[3]);
                MMA16816(acc2[gp * 2 + 1], al, bh[2], bh[3]);
            }
        }
    }

    // ---- Epilogue2 + GEMV: s = relu(h2+b2) @ W3 + b3 ----------------------
    {
        int r0 = m0 + g, r1 = r0 + 8;
        float s0 = 0.0f, s1 = 0.0f;
#pragma unroll
        for (int nt = 0; nt < 8; nt++) {
            int n = n02 + nt * 8 + tq * 2;
            float w3a = W3s[n], w3b = W3s[n + 1];
            float ba = b2s[n], bb = b2s[n + 1];
            s0 = fmaf(fmaxf(acc2[nt][0] + ba, 0.0f), w3a, s0);
            s0 = fmaf(fmaxf(acc2[nt][1] + bb, 0.0f), w3b, s0);
            s1 = fmaf(fmaxf(acc2[nt][2] + ba, 0.0f), w3a, s1);
            s1 = fmaf(fmaxf(acc2[nt][3] + bb, 0.0f), w3b, s1);
        }
        s0 += __shfl_xor_sync(0xffffffffu, s0, 1);
        s0 += __shfl_xor_sync(0xffffffffu, s0, 2);
        s1 += __shfl_xor_sync(0xffffffffu, s1, 1);
        s1 += __shfl_xor_sync(0xffffffffu, s1, 2);
        if (tq == 0) {
            sred[r0 * 2 + (wid >> 2)] = s0;
            sred[r1 * 2 + (wid >> 2)] = s1;
        }
    }
    __syncthreads();
    if (t < TBP) out[pair0 + t] = sred[t * 2] + sred[t * 2 + 1] + b3[0];
}

// --------------------------- launcher --------------------------------------
extern "C" void kernel_launch(void* const* d_in, const int* in_sizes, int n_in,
                              void* d_out, int out_size) {
    const float* x  = (const float*)d_in[0];
    const int* ei   = (const int*)d_in[1];
    const int* ep   = (const int*)d_in[2];
    const float* W1 = (const float*)d_in[3];
    const float* b1 = (const float*)d_in[4];
    const float* W2 = (const float*)d_in[5];
    const float* b2 = (const float*)d_in[6];
    const float* W3 = (const float*)d_in[7];
    const float* b3 = (const float*)d_in[8];
    float* out      = (float*)d_out;

    int E = in_sizes[1] / 2;
    int P = in_sizes[2] / 2;

    build_bits_kernel<<<(E + 255) / 256, 256>>>(ei, E);
    node_stats_kernel<<<NNODES / 8, 256>>>(x);
    combine_w_kernel<<<128, 256>>>(W1);
    w_split_kernel<<<384, 256>>>(W1, W2);
    pre_gemm_kernel<<<dim3(NNODES / 32, 2), 256>>>(x);

    cudaFuncSetAttribute(pair3_kernel,
                         cudaFuncAttributeMaxDynamicSharedMemorySize, SMEM2);
    pair3_kernel<<<P / TBP, 256, SMEM2>>>(x, ep, W1, b1, b2, W3, b3, out);
}

// round 14
// speedup vs baseline: 1.9228x; 1.1485x over previous
#include <cuda_runtime.h>
#include <cuda_bf16.h>
#include <cstdint>
#include <math.h>

// ---------------------------------------------------------------------------
// PairwiseMLPLinkPredictor — GB300 sm_103a (sm_103 base target: mma.sync HMMA)
//
// All GEMMs (pre-node GEMM + pair GEMM1/GEMM2): fp32 split into bf16 hi+lo,
//   D = Ah*Bh + Ah*Bl + Al*Bh   (fp32 accum, rel err ~1e-5)
// ---------------------------------------------------------------------------

#define NNODES   8192
#define WORDS    128
#define INCH     128
#define HID      256
#define HID2     128
#define TBP      64           // pairs per CTA
#define EPSF     1e-8f

// --------------------------- device scratch --------------------------------
__device__ unsigned long long g_bits[(size_t)NNODES * WORDS];   // 8 MB
__device__ float g_invlog[NNODES];
__device__ float g_invdeg[NNODES];
__device__ float g_norm[NNODES];
__device__ float g_Wa[INCH * HID];
__device__ float g_Wb[INCH * HID];
__device__ float g_preu[(size_t)NNODES * HID];                  // 8 MB
__device__ float g_prev[(size_t)NNODES * HID];                  // 8 MB
// Pre-split bf16 weights, plain [n][k] row-major, k contiguous.
__device__ unsigned short g_B1hi[256 * 256];   // W1 rows 256:512 transposed
__device__ unsigned short g_B1lo[256 * 256];
__device__ unsigned short g_B2hi[128 * 256];   // W2^T
__device__ unsigned short g_B2lo[128 * 256];
// x and [Wa|Wb] splits for the node-level GEMM
__device__ unsigned short g_Xhi[(size_t)NNODES * INCH];   // 2 MB
__device__ unsigned short g_Xlo[(size_t)NNODES * INCH];
__device__ unsigned short g_WabHi[512 * 128];  // [n=512][k=128]; n<256: Wa, else Wb
__device__ unsigned short g_WabLo[512 * 128];

// --------------------------- helpers ---------------------------------------
__device__ __forceinline__ uint32_t smem_u32(const void* p) {
    uint32_t a;
    asm("{ .reg .u64 t; cvta.to.shared.u64 t, %1; cvt.u32.u64 %0, t; }"
        : "=r"(a) : "l"(p));
    return a;
}

#define LDSM_X4(r, addr) \
    asm volatile("ldmatrix.sync.aligned.m8n8.x4.shared.b16 {%0,%1,%2,%3}, [%4];" \
        : "=r"((r)[0]), "=r"((r)[1]), "=r"((r)[2]), "=r"((r)[3]) : "r"(addr))

#define MMA16816(c, a, b0, b1) \
    asm volatile("mma.sync.aligned.m16n8k16.row.col.f32.bf16.bf16.f32 " \
        "{%0,%1,%2,%3}, {%4,%5,%6,%7}, {%8,%9}, {%0,%1,%2,%3};" \
        : "+f"((c)[0]), "+f"((c)[1]), "+f"((c)[2]), "+f"((c)[3]) \
        : "r"((a)[0]), "r"((a)[1]), "r"((a)[2]), "r"((a)[3]), "r"(b0), "r"(b1))

__device__ __forceinline__ void bsplit(float v, unsigned short& h, unsigned short& l) {
    __nv_bfloat16 hb = __float2bfloat16(v);
    __nv_bfloat16 lb = __float2bfloat16(v - __bfloat162float(hb));
    h = *reinterpret_cast<unsigned short*>(&hb);
    l = *reinterpret_cast<unsigned short*>(&lb);
}
__device__ __forceinline__ uint32_t pack2(unsigned short a, unsigned short b) {
    return (uint32_t)a | ((uint32_t)b << 16);
}

// --------------------------- prep kernels ----------------------------------
__global__ void build_bits_kernel(const int* __restrict__ ei, int E) {
    int e = blockIdx.x * blockDim.x + threadIdx.x;
    if (e >= E) return;
    int u = ei[e];
    int v = ei[E + e];
    if (u == v) return;
    atomicOr(&g_bits[(size_t)u * WORDS + (v >> 6)], 1ull << (v & 63));
}

__global__ void node_stats_kernel(const float* __restrict__ x) {
    int node = blockIdx.x * 8 + (threadIdx.x >> 5);
    int lane = threadIdx.x & 31;
    const unsigned long long* row = g_bits + (size_t)node * WORDS;
    int cnt = 0;
#pragma unroll
    for (int i = 0; i < 4; i++) cnt += __popcll(row[i * 32 + lane]);
    float4 a = ((const float4*)(x + (size_t)node * INCH))[lane];
    float nrm = a.x * a.x + a.y * a.y + a.z * a.z + a.w * a.w;
#pragma unroll
    for (int o = 16; o; o >>= 1) {
        cnt += __shfl_xor_sync(0xffffffffu, cnt, o);
        nrm += __shfl_xor_sync(0xffffffffu, nrm, o);
    }
    if (lane == 0) {
        float deg = (float)cnt;
        g_norm[node]   = sqrtf(nrm);
        g_invlog[node] = (cnt > 1) ? (1.0f / logf(deg)) : 0.0f;
        g_invdeg[node] = (cnt > 0) ? (1.0f / deg) : 0.0f;
    }
}

__global__ void combine_w_kernel(const float* __restrict__ W1) {
    int i = blockIdx.x * 256 + threadIdx.x;
    float we = W1[512 * HID + i];
    g_Wa[i] = W1[i] + we;
    g_Wb[i] = W1[128 * HID + i] + we;
}

// Split + transpose W1 rows 256:512 -> g_B1 [n=256][k=256]; W2 -> g_B2 [n=128][k=256]
__global__ void w_split_kernel(const float* __restrict__ W1,
                               const float* __restrict__ W2) {
    int idx = blockIdx.x * 256 + threadIdx.x;
    if (idx < 65536) {
        int n = idx >> 8, k = idx & 255;
        float v = W1[(size_t)(256 + k) * HID + n];
        unsigned short h, l; bsplit(v, h, l);
        g_B1hi[n * 256 + k] = h;
        g_B1lo[n * 256 + k] = l;
    } else if (idx < 98304) {
        int j = idx - 65536;
        int n = j >> 8, k = j & 255;
        float v = W2[(size_t)k * HID2 + n];
        unsigned short h, l; bsplit(v, h, l);
        g_B2hi[n * 256 + k] = h;
        g_B2lo[n * 256 + k] = l;
    }
}

// Split x into bf16 hi/lo (row-major [node][k])
__global__ void x_split_kernel(const float* __restrict__ x) {
    int i = blockIdx.x * 256 + threadIdx.x;   // 0 .. 1048575
    float v = x[i];
    unsigned short h, l; bsplit(v, h, l);
    g_Xhi[i] = h;
    g_Xlo[i] = l;
}

// Split+transpose [Wa|Wb] (each [k=128][n=256]) -> g_Wab [n=512][k=128]
__global__ void wab_split_kernel() {
    int idx = blockIdx.x * 256 + threadIdx.x;  // 0 .. 65535
    int n = idx >> 7, k = idx & 127;
    float v = (n < 256) ? g_Wa[k * HID + n] : g_Wb[k * HID + (n - 256)];
    unsigned short h, l; bsplit(v, h, l);
    g_WabHi[n * 128 + k] = h;
    g_WabLo[n * 128 + k] = l;
}

// --------------------------- pre GEMM via mma.sync -------------------------
// [preu|prev][8192, 256] = x[8192,128] @ [Wa|Wb][128, 512]
// A smem: 64 rows x 136 bf16 (272 B/row); B smem: 256 rows x 72 bf16 (144 B)
#define PA_STRIDE 272
#define PB_STRIDE 144
#define OFF_PAH 0          // 17408
#define OFF_PAL 17408      // 17408
#define OFF_PBH 34816      // 36864
#define OFF_PBL 71680      // 36864
#define SMEM_PRE 108544

__global__ __launch_bounds__(256, 1) void pre_mma_kernel() {
    extern __shared__ char sm[];
    uint32_t smu = smem_u32(sm);
    int t = threadIdx.x;
    int wid = t >> 5, lane = t & 31;
    int g = lane >> 2, tq = lane & 3;
    int row0 = blockIdx.x * 64;

    // load A tile hi/lo: 64 rows x 128 bf16 (16 uint4/row)
    for (int i = t; i < 1024; i += 256) {
        int r = i >> 4, q = i & 15;
        ((uint4*)(sm + OFF_PAH))[r * 17 + q] = ((const uint4*)g_Xhi)[(size_t)(row0 + r) * 16 + q];
        ((uint4*)(sm + OFF_PAL))[r * 17 + q] = ((const uint4*)g_Xlo)[(size_t)(row0 + r) * 16 + q];
    }

    int m0 = (wid & 3) * 16;
    int n0 = (wid >> 2) * 128;
    uint32_t aAh = smu + OFF_PAH + (m0 + (lane & 15)) * PA_STRIDE + ((lane >> 4) & 1) * 16;
    uint32_t aAl = aAh + (OFF_PAL - OFF_PAH);
    uint32_t bRow = (lane & 7) + ((lane >> 4) & 1) * 8;
    uint32_t bColH = ((lane >> 3) & 1) * 16;

    for (int no = 0; no < 2; no++) {
        float acc[16][4];
#pragma unroll
        for (int i = 0; i < 16; i++)
#pragma unroll
            for (int j = 0; j < 4; j++) acc[i][j] = 0.0f;

        for (int kc = 0; kc < 2; kc++) {
            __syncthreads();
            for (int i = t; i < 2048; i += 256) {
                int n = i >> 3, q = i & 7;
                ((uint4*)(sm + OFF_PBH))[n * 9 + q] =
                    ((const uint4*)g_WabHi)[(size_t)(no * 256 + n) * 16 + kc * 8 + q];
                ((uint4*)(sm + OFF_PBL))[n * 9 + q] =
                    ((const uint4*)g_WabLo)[(size_t)(no * 256 + n) * 16 + kc * 8 + q];
            }
            __syncthreads();
#pragma unroll
            for (int ks = 0; ks < 4; ks++) {
                uint32_t kb = (kc * 64 + ks * 16) * 2;
                uint32_t ah[4], al[4];
                LDSM_X4(ah, aAh + kb);
                LDSM_X4(al, aAl + kb);
#pragma unroll
                for (int gp = 0; gp < 8; gp++) {
                    uint32_t baddr = smu + OFF_PBH + (n0 + gp * 16 + bRow) * PB_STRIDE + ks * 32 + bColH;
                    uint32_t bh[4], bl[4];
                    LDSM_X4(bh, baddr);
                    LDSM_X4(bl, baddr + (OFF_PBL - OFF_PBH));
                    MMA16816(acc[gp * 2],     ah, bh[0], bh[1]);
                    MMA16816(acc[gp * 2],     ah, bl[0], bl[1]);
                    MMA16816(acc[gp * 2],     al, bh[0], bh[1]);
                    MMA16816(acc[gp * 2 + 1], ah, bh[2], bh[3]);
                    MMA16816(acc[gp * 2 + 1], ah, bl[2], bl[3]);
                    MMA16816(acc[gp * 2 + 1], al, bh[2], bh[3]);
                }
            }
        }
        float* dst = no ? g_prev : g_preu;
        int r0 = row0 + m0 + g, r1 = r0 + 8;
#pragma unroll
        for (int nt = 0; nt < 16; nt++) {
            int n = n0 + nt * 8 + tq * 2;
            *(float2*)(dst + (size_t)r0 * HID + n) = make_float2(acc[nt][0], acc[nt][1]);
            *(float2*)(dst + (size_t)r1 * HID + n) = make_float2(acc[nt][2], acc[nt][3]);
        }
    }
}

// --------------------------- main pair kernel (mma.sync) -------------------
// A buffers: 64 rows x 264 bf16 (528 B/row); B buffers: 256 rows x 72 bf16
#define A_STRIDE 528
#define B_STRIDE 144
#define OFF_A1HI 0
#define OFF_A1LO 33792
#define OFF_BHI  67584
#define OFF_BLO  104448
#define OFF_US   141312
#define OFF_VS   141568
#define OFF_DOT  141824
#define OFF_SCC  142848
#define OFF_SCN  143104
#define OFF_SCA  143360
#define OFF_SCR  143616
#define OFF_WEX  143872
#define OFF_B1S  147968
#define OFF_B2S  148992
#define OFF_W3S  149504
#define OFF_SRED 150016
#define SMEM2    150528

__global__ __launch_bounds__(256, 1) void pair3_kernel(
    const float* __restrict__ x,
    const int* __restrict__ pairs,
    const float* __restrict__ W1,
    const float* __restrict__ b1,
    const float* __restrict__ b2,
    const float* __restrict__ W3,
    const float* __restrict__ b3,
    float* __restrict__ out) {
    extern __shared__ char sm[];
    uint32_t smu = smem_u32(sm);
    char*  A1hi = sm + OFF_A1HI;
    char*  A1lo = sm + OFF_A1LO;
    int*   us   = (int*)(sm + OFF_US);
    int*   vs   = (int*)(sm + OFF_VS);
    float* dotp = (float*)(sm + OFF_DOT);
    float* scC  = (float*)(sm + OFF_SCC);
    float* scN  = (float*)(sm + OFF_SCN);
    float* scA  = (float*)(sm + OFF_SCA);
    float* scR  = (float*)(sm + OFF_SCR);
    float* Wex  = (float*)(sm + OFF_WEX);
    float* b1s  = (float*)(sm + OFF_B1S);
    float* b2s  = (float*)(sm + OFF_B2S);
    float* W3s  = (float*)(sm + OFF_W3S);
    float* sred = (float*)(sm + OFF_SRED);

    int t = threadIdx.x;
    int wid = t >> 5, lane = t & 31;
    int g = lane >> 2, tq = lane & 3;
    int pair0 = blockIdx.x * TBP;

    if (t < TBP) {
        us[t] = pairs[2 * (pair0 + t)];
        vs[t] = pairs[2 * (pair0 + t) + 1];
    }
    for (int i = t; i < 1024; i += 256) Wex[i] = W1[640 * HID + i];
    b1s[t] = b1[t];
    if (t < 128) { b2s[t] = b2[t]; W3s[t] = W3[t]; }
    __syncthreads();

    // ---- Phase A: features -> A1 hi/lo row-major bf16 ---------------------
    {
        int m = t & 63, s = t >> 6;
        const float4* xu4 = (const float4*)(x + (size_t)us[m] * INCH + s * 32);
        const float4* xv4 = (const float4*)(x + (size_t)vs[m] * INCH + s * 32);
        unsigned short* Ah = (unsigned short*)(A1hi + m * A_STRIDE);
        unsigned short* Al = (unsigned short*)(A1lo + m * A_STRIDE);
        float dot = 0.0f;
#pragma unroll
        for (int i = 0; i < 8; i++) {
            float4 a = xu4[i], b = xv4[i];
            int f = s * 32 + i * 4;
            float p0 = a.x * b.x, p1 = a.y * b.y, p2 = a.z * b.z, p3 = a.w * b.w;
            dot += p0 + p1 + p2 + p3;
            unsigned short h0,l0,h1,l1,h2,l2,h3,l3;
            bsplit(p0,h0,l0); bsplit(p1,h1,l1); bsplit(p2,h2,l2); bsplit(p3,h3,l3);
            *(uint2*)(Ah + f)       = make_uint2(pack2(h0,h1), pack2(h2,h3));
            *(uint2*)(Al + f)       = make_uint2(pack2(l0,l1), pack2(l2,l3));
            float q0 = fabsf(a.x-b.x), q1 = fabsf(a.y-b.y), q2 = fabsf(a.z-b.z), q3 = fabsf(a.w-b.w);
            bsplit(q0,h0,l0); bsplit(q1,h1,l1); bsplit(q2,h2,l2); bsplit(q3,h3,l3);
            *(uint2*)(Ah + 128 + f) = make_uint2(pack2(h0,h1), pack2(h2,h3));
            *(uint2*)(Al + 128 + f) = make_uint2(pack2(l0,l1), pack2(l2,l3));
        }
        dotp[s * 64 + m] = dot;
    }
    __syncthreads();
    if (t < TBP) {
        float d = dotp[t] + dotp[64 + t] + dotp[128 + t] + dotp[192 + t];
        float nn = g_norm[us[t]] * g_norm[vs[t]];
        scC[t] = d / fmaxf(nn, EPSF);
    }

    // ---- Phase B: common-neighbor stats (warp per 8 pairs) ----------------
    {
        for (int pp = 0; pp < 8; pp++) {
            int m = wid * 8 + pp;
            const unsigned long long* bu = g_bits + (size_t)us[m] * WORDS;
            const unsigned long long* bv = g_bits + (size_t)vs[m] * WORDS;
            int cn = 0; float aa = 0.0f, ra = 0.0f;
#pragma unroll
            for (int it = 0; it < 4; it++) {
                int wi = it * 32 + lane;
                unsigned long long c = bu[wi] & bv[wi];
                cn += __popcll(c);
                while (c) {
                    int b = __ffsll((long long)c) - 1;
                    c &= c - 1;
                    int idx = wi * 64 + b;
                    aa += g_invlog[idx];
                    ra += g_invdeg[idx];
                }
            }
#pragma unroll
            for (int o = 16; o; o >>= 1) {
                cn += __shfl_xor_sync(0xffffffffu, cn, o);
                aa += __shfl_xor_sync(0xffffffffu, aa, o);
                ra += __shfl_xor_sync(0xffffffffu, ra, o);
            }
            if (lane == 0) { scN[m] = (float)cn; scA[m] = aa; scR[m] = ra; }
        }
    }

    // ---- GEMM1: h1[64x256] via mma.sync, K chunks of 64 -------------------
    int m0 = (wid & 3) * 16;
    int n0 = (wid >> 2) * 128;
    float acc1[16][4];
#pragma unroll
    for (int i = 0; i < 16; i++)
#pragma unroll
        for (int j = 0; j < 4; j++) acc1[i][j] = 0.0f;

    uint32_t aAh = smu + OFF_A1HI + (m0 + (lane & 15)) * A_STRIDE + ((lane >> 4) & 1) * 16;
    uint32_t aAl = aAh + (OFF_A1LO - OFF_A1HI);
    uint32_t bRow = (lane & 7) + ((lane >> 4) & 1) * 8;
    uint32_t bColH = ((lane >> 3) & 1) * 16;

    for (int kc = 0; kc < 4; kc++) {
        __syncthreads();
        for (int i = t; i < 2048; i += 256) {
            int n = i >> 3, q = i & 7;
            ((uint4*)(sm + OFF_BHI))[n * 9 + q] = ((const uint4*)g_B1hi)[n * 32 + kc * 8 + q];
            ((uint4*)(sm + OFF_BLO))[n * 9 + q] = ((const uint4*)g_B1lo)[n * 32 + kc * 8 + q];
        }
        __syncthreads();
#pragma unroll
        for (int ks = 0; ks < 4; ks++) {
            uint32_t kb = (kc * 64 + ks * 16) * 2;
            uint32_t ah[4], al[4];
            LDSM_X4(ah, aAh + kb);
            LDSM_X4(al, aAl + kb);
#pragma unroll
            for (int gp = 0; gp < 8; gp++) {
                uint32_t baddr = smu + OFF_BHI + (n0 + gp * 16 + bRow) * B_STRIDE + ks * 32 + bColH;
                uint32_t bh[4], bl[4];
                LDSM_X4(bh, baddr);
                LDSM_X4(bl, baddr + (OFF_BLO - OFF_BHI));
                MMA16816(acc1[gp * 2],     ah, bh[0], bh[1]);
                MMA16816(acc1[gp * 2],     ah, bl[0], bl[1]);
                MMA16816(acc1[gp * 2],     al, bh[0], bh[1]);
                MMA16816(acc1[gp * 2 + 1], ah, bh[2], bh[3]);
                MMA16816(acc1[gp * 2 + 1], ah, bl[2], bl[3]);
                MMA16816(acc1[gp * 2 + 1], al, bh[2], bh[3]);
            }
        }
    }
    __syncthreads();

    // ---- Epilogue1: h1 = relu(D1 + pre_u + pre_v + b1 + scalars) -> A1 ----
    {
        int r0 = m0 + g, r1 = r0 + 8;
        int u0 = us[r0], v0 = vs[r0], u1 = us[r1], v1 = vs[r1];
        float c0m = scC[r0], n0m = scN[r0], a0m = scA[r0], q0m = scR[r0];
        float c1m = scC[r1], n1m = scN[r1], a1m = scA[r1], q1m = scR[r1];
        unsigned short* Ah0 = (unsigned short*)(A1hi + r0 * A_STRIDE);
        unsigned short* Al0 = (unsigned short*)(A1lo + r0 * A_STRIDE);
        unsigned short* Ah1 = (unsigned short*)(A1hi + r1 * A_STRIDE);
        unsigned short* Al1 = (unsigned short*)(A1lo + r1 * A_STRIDE);
#pragma unroll
        for (int nt = 0; nt < 16; nt++) {
            int n = n0 + nt * 8 + tq * 2;
            float2 pu0 = *(const float2*)(g_preu + (size_t)u0 * HID + n);
            float2 pv0 = *(const float2*)(g_prev + (size_t)v0 * HID + n);
            float2 pu1 = *(const float2*)(g_preu + (size_t)u1 * HID + n);
            float2 pv1 = *(const float2*)(g_prev + (size_t)v1 * HID + n);
            float w0a = Wex[n], w0b = Wex[n + 1];
            float w1a = Wex[256 + n], w1b = Wex[256 + n + 1];
            float w2a = Wex[512 + n], w2b = Wex[512 + n + 1];
            float w3a = Wex[768 + n], w3b = Wex[768 + n + 1];
            float ba = b1s[n], bb = b1s[n + 1];
            float h00 = acc1[nt][0] + pu0.x + pv0.x + ba;
            h00 = fmaf(c0m, w0a, h00); h00 = fmaf(n0m, w1a, h00);
            h00 = fmaf(a0m, w2a, h00); h00 = fmaf(q0m, w3a, h00);
            float h01 = acc1[nt][1] + pu0.y + pv0.y + bb;
            h01 = fmaf(c0m, w0b, h01); h01 = fmaf(n0m, w1b, h01);
            h01 = fmaf(a0m, w2b, h01); h01 = fmaf(q0m, w3b, h01);
            float h10 = acc1[nt][2] + pu1.x + pv1.x + ba;
            h10 = fmaf(c1m, w0a, h10); h10 = fmaf(n1m, w1a, h10);
            h10 = fmaf(a1m, w2a, h10); h10 = fmaf(q1m, w3a, h10);
            float h11 = acc1[nt][3] + pu1.y + pv1.y + bb;
            h11 = fmaf(c1m, w0b, h11); h11 = fmaf(n1m, w1b, h11);
            h11 = fmaf(a1m, w2b, h11); h11 = fmaf(q1m, w3b, h11);
            h00 = fmaxf(h00, 0.0f); h01 = fmaxf(h01, 0.0f);
            h10 = fmaxf(h10, 0.0f); h11 = fmaxf(h11, 0.0f);
            unsigned short hh0, ll0, hh1, ll1;
            bsplit(h00, hh0, ll0); bsplit(h01, hh1, ll1);
            *(uint32_t*)(Ah0 + n) = pack2(hh0, hh1);
            *(uint32_t*)(Al0 + n) = pack2(ll0, ll1);
            bsplit(h10, hh0, ll0); bsplit(h11, hh1, ll1);
            *(uint32_t*)(Ah1 + n) = pack2(hh0, hh1);
            *(uint32_t*)(Al1 + n) = pack2(ll0, ll1);
        }
    }

    // ---- GEMM2: h2[64x128] = h1 @ W2 --------------------------------------
    int n02 = (wid >> 2) * 64;
    float acc2[8][4];
#pragma unroll
    for (int i = 0; i < 8; i++)
#pragma unroll
        for (int j = 0; j < 4; j++) acc2[i][j] = 0.0f;

    for (int kc = 0; kc < 4; kc++) {
        __syncthreads();
        for (int i = t; i < 1024; i += 256) {
            int n = i >> 3, q = i & 7;
            ((uint4*)(sm + OFF_BHI))[n * 9 + q] = ((const uint4*)g_B2hi)[n * 32 + kc * 8 + q];
            ((uint4*)(sm + OFF_BLO))[n * 9 + q] = ((const uint4*)g_B2lo)[n * 32 + kc * 8 + q];
        }
        __syncthreads();
#pragma unroll
        for (int ks = 0; ks < 4; ks++) {
            uint32_t kb = (kc * 64 + ks * 16) * 2;
            uint32_t ah[4], al[4];
            LDSM_X4(ah, aAh + kb);
            LDSM_X4(al, aAl + kb);
#pragma unroll
            for (int gp = 0; gp < 4; gp++) {
                uint32_t baddr = smu + OFF_BHI + (n02 + gp * 16 + bRow) * B_STRIDE + ks * 32 + bColH;
                uint32_t bh[4], bl[4];
                LDSM_X4(bh, baddr);
                LDSM_X4(bl, baddr + (OFF_BLO - OFF_BHI));
                MMA16816(acc2[gp * 2],     ah, bh[0], bh[1]);
                MMA16816(acc2[gp * 2],     ah, bl[0], bl[1]);
                MMA16816(acc2[gp * 2],     al, bh[0], bh[1]);
                MMA16816(acc2[gp * 2 + 1], ah, bh[2], bh[3]);
                MMA16816(acc2[gp * 2 + 1], ah, bl[2], bl[3]);
                MMA16816(acc2[gp * 2 + 1], al, bh[2], bh[3]);
            }
        }
    }

    // ---- Epilogue2 + GEMV: s = relu(h2+b2) @ W3 + b3 ----------------------
    {
        int r0 = m0 + g, r1 = r0 + 8;
        float s0 = 0.0f, s1 = 0.0f;
#pragma unroll
        for (int nt = 0; nt < 8; nt++) {
            int n = n02 + nt * 8 + tq * 2;
            float w3a = W3s[n], w3b = W3s[n + 1];
            float ba = b2s[n], bb = b2s[n + 1];
            s0 = fmaf(fmaxf(acc2[nt][0] + ba, 0.0f), w3a, s0);
            s0 = fmaf(fmaxf(acc2[nt][1] + bb, 0.0f), w3b, s0);
            s1 = fmaf(fmaxf(acc2[nt][2] + ba, 0.0f), w3a, s1);
            s1 = fmaf(fmaxf(acc2[nt][3] + bb, 0.0f), w3b, s1);
        }
        s0 += __shfl_xor_sync(0xffffffffu, s0, 1);
        s0 += __shfl_xor_sync(0xffffffffu, s0, 2);
        s1 += __shfl_xor_sync(0xffffffffu, s1, 1);
        s1 += __shfl_xor_sync(0xffffffffu, s1, 2);
        if (tq == 0) {
            sred[r0 * 2 + (wid >> 2)] = s0;
            sred[r1 * 2 + (wid >> 2)] = s1;
        }
    }
    __syncthreads();
    if (t < TBP) out[pair0 + t] = sred[t * 2] + sred[t * 2 + 1] + b3[0];
}

// --------------------------- launcher --------------------------------------
extern "C" void kernel_launch(void* const* d_in, const int* in_sizes, int n_in,
                              void* d_out, int out_size) {
    const float* x  = (const float*)d_in[0];
    const int* ei   = (const int*)d_in[1];
    const int* ep   = (const int*)d_in[2];
    const float* W1 = (const float*)d_in[3];
    const float* b1 = (const float*)d_in[4];
    const float* W2 = (const float*)d_in[5];
    const float* b2 = (const float*)d_in[6];
    const float* W3 = (const float*)d_in[7];
    const float* b3 = (const float*)d_in[8];
    float* out      = (float*)d_out;

    int E = in_sizes[1] / 2;
    int P = in_sizes[2] / 2;

    build_bits_kernel<<<(E + 255) / 256, 256>>>(ei, E);
    node_stats_kernel<<<NNODES / 8, 256>>>(x);
    combine_w_kernel<<<128, 256>>>(W1);
    w_split_kernel<<<384, 256>>>(W1, W2);
    x_split_kernel<<<4096, 256>>>(x);
    wab_split_kernel<<<256, 256>>>();

    cudaFuncSetAttribute(pre_mma_kernel,
                         cudaFuncAttributeMaxDynamicSharedMemorySize, SMEM_PRE);
    pre_mma_kernel<<<NNODES / 64, 256, SMEM_PRE>>>();

    cudaFuncSetAttribute(pair3_kernel,
                         cudaFuncAttributeMaxDynamicSharedMemorySize, SMEM2);
    pair3_kernel<<<P / TBP, 256, SMEM2>>>(x, ep, W1, b1, b2, W3, b3, out);
}

// round 17
// speedup vs baseline: 2.1171x; 1.1011x over previous
#include <cuda_runtime.h>
#include <cuda_bf16.h>
#include <cstdint>
#include <math.h>

// ---------------------------------------------------------------------------
// PairwiseMLPLinkPredictor — GB300 sm_103a (sm_103 base target: mma.sync HMMA)
//
// All GEMMs: fp32 split into bf16 hi+lo, D = Ah*Bh + Ah*Bl + Al*Bh (fp32 acc).
// R14: pair3 MMA chains interleaved (acc_e/acc_o) + register double-buffered
//      B tiles to hide global->smem latency.
// ---------------------------------------------------------------------------

#define NNODES   8192
#define WORDS    128
#define INCH     128
#define HID      256
#define HID2     128
#define TBP      64           // pairs per CTA
#define EPSF     1e-8f

// --------------------------- device scratch --------------------------------
__device__ unsigned long long g_bits[(size_t)NNODES * WORDS];   // 8 MB
__device__ float g_invlog[NNODES];
__device__ float g_invdeg[NNODES];
__device__ float g_norm[NNODES];
__device__ float g_Wa[INCH * HID];
__device__ float g_Wb[INCH * HID];
__device__ float g_preu[(size_t)NNODES * HID];                  // 8 MB
__device__ float g_prev[(size_t)NNODES * HID];                  // 8 MB
__device__ unsigned short g_B1hi[256 * 256];
__device__ unsigned short g_B1lo[256 * 256];
__device__ unsigned short g_B2hi[128 * 256];
__device__ unsigned short g_B2lo[128 * 256];
__device__ unsigned short g_Xhi[(size_t)NNODES * INCH];
__device__ unsigned short g_Xlo[(size_t)NNODES * INCH];
__device__ unsigned short g_WabHi[512 * 128];
__device__ unsigned short g_WabLo[512 * 128];

// --------------------------- helpers ---------------------------------------
__device__ __forceinline__ uint32_t smem_u32(const void* p) {
    uint32_t a;
    asm("{ .reg .u64 t; cvta.to.shared.u64 t, %1; cvt.u32.u64 %0, t; }"
        : "=r"(a) : "l"(p));
    return a;
}

#define LDSM_X4(r, addr) \
    asm volatile("ldmatrix.sync.aligned.m8n8.x4.shared.b16 {%0,%1,%2,%3}, [%4];" \
        : "=r"((r)[0]), "=r"((r)[1]), "=r"((r)[2]), "=r"((r)[3]) : "r"(addr))

#define MMA16816(c, a, b0, b1) \
    asm volatile("mma.sync.aligned.m16n8k16.row.col.f32.bf16.bf16.f32 " \
        "{%0,%1,%2,%3}, {%4,%5,%6,%7}, {%8,%9}, {%0,%1,%2,%3};" \
        : "+f"((c)[0]), "+f"((c)[1]), "+f"((c)[2]), "+f"((c)[3]) \
        : "r"((a)[0]), "r"((a)[1]), "r"((a)[2]), "r"((a)[3]), "r"(b0), "r"(b1))

__device__ __forceinline__ void bsplit(float v, unsigned short& h, unsigned short& l) {
    __nv_bfloat16 hb = __float2bfloat16(v);
    __nv_bfloat16 lb = __float2bfloat16(v - __bfloat162float(hb));
    h = *reinterpret_cast<unsigned short*>(&hb);
    l = *reinterpret_cast<unsigned short*>(&lb);
}
__device__ __forceinline__ uint32_t pack2(unsigned short a, unsigned short b) {
    return (uint32_t)a | ((uint32_t)b << 16);
}

// --------------------------- prep kernels ----------------------------------
__global__ void build_bits_kernel(const int* __restrict__ ei, int E) {
    int e = blockIdx.x * blockDim.x + threadIdx.x;
    if (e >= E) return;
    int u = ei[e];
    int v = ei[E + e];
    if (u == v) return;
    atomicOr(&g_bits[(size_t)u * WORDS + (v >> 6)], 1ull << (v & 63));
}

__global__ void node_stats_kernel(const float* __restrict__ x) {
    int node = blockIdx.x * 8 + (threadIdx.x >> 5);
    int lane = threadIdx.x & 31;
    const unsigned long long* row = g_bits + (size_t)node * WORDS;
    int cnt = 0;
#pragma unroll
    for (int i = 0; i < 4; i++) cnt += __popcll(row[i * 32 + lane]);
    float4 a = ((const float4*)(x + (size_t)node * INCH))[lane];
    float nrm = a.x * a.x + a.y * a.y + a.z * a.z + a.w * a.w;
#pragma unroll
    for (int o = 16; o; o >>= 1) {
        cnt += __shfl_xor_sync(0xffffffffu, cnt, o);
        nrm += __shfl_xor_sync(0xffffffffu, nrm, o);
    }
    if (lane == 0) {
        float deg = (float)cnt;
        g_norm[node]   = sqrtf(nrm);
        g_invlog[node] = (cnt > 1) ? (1.0f / logf(deg)) : 0.0f;
        g_invdeg[node] = (cnt > 0) ? (1.0f / deg) : 0.0f;
    }
}

__global__ void combine_w_kernel(const float* __restrict__ W1) {
    int i = blockIdx.x * 256 + threadIdx.x;
    float we = W1[512 * HID + i];
    g_Wa[i] = W1[i] + we;
    g_Wb[i] = W1[128 * HID + i] + we;
}

__global__ void w_split_kernel(const float* __restrict__ W1,
                               const float* __restrict__ W2) {
    int idx = blockIdx.x * 256 + threadIdx.x;
    if (idx < 65536) {
        int n = idx >> 8, k = idx & 255;
        float v = W1[(size_t)(256 + k) * HID + n];
        unsigned short h, l; bsplit(v, h, l);
        g_B1hi[n * 256 + k] = h;
        g_B1lo[n * 256 + k] = l;
    } else if (idx < 98304) {
        int j = idx - 65536;
        int n = j >> 8, k = j & 255;
        float v = W2[(size_t)k * HID2 + n];
        unsigned short h, l; bsplit(v, h, l);
        g_B2hi[n * 256 + k] = h;
        g_B2lo[n * 256 + k] = l;
    }
}

__global__ void x_split_kernel(const float* __restrict__ x) {
    int i = blockIdx.x * 256 + threadIdx.x;
    float v = x[i];
    unsigned short h, l; bsplit(v, h, l);
    g_Xhi[i] = h;
    g_Xlo[i] = l;
}

__global__ void wab_split_kernel() {
    int idx = blockIdx.x * 256 + threadIdx.x;
    int n = idx >> 7, k = idx & 127;
    float v = (n < 256) ? g_Wa[k * HID + n] : g_Wb[k * HID + (n - 256)];
    unsigned short h, l; bsplit(v, h, l);
    g_WabHi[n * 128 + k] = h;
    g_WabLo[n * 128 + k] = l;
}

// --------------------------- pre GEMM via mma.sync -------------------------
#define PA_STRIDE 272
#define PB_STRIDE 144
#define OFF_PAH 0
#define OFF_PAL 17408
#define OFF_PBH 34816
#define OFF_PBL 71680
#define SMEM_PRE 108544

__global__ __launch_bounds__(256, 1) void pre_mma_kernel() {
    extern __shared__ char sm[];
    uint32_t smu = smem_u32(sm);
    int t = threadIdx.x;
    int wid = t >> 5, lane = t & 31;
    int g = lane >> 2, tq = lane & 3;
    int row0 = blockIdx.x * 64;

    for (int i = t; i < 1024; i += 256) {
        int r = i >> 4, q = i & 15;
        ((uint4*)(sm + OFF_PAH))[r * 17 + q] = ((const uint4*)g_Xhi)[(size_t)(row0 + r) * 16 + q];
        ((uint4*)(sm + OFF_PAL))[r * 17 + q] = ((const uint4*)g_Xlo)[(size_t)(row0 + r) * 16 + q];
    }

    int m0 = (wid & 3) * 16;
    int n0 = (wid >> 2) * 128;
    uint32_t aAh = smu + OFF_PAH + (m0 + (lane & 15)) * PA_STRIDE + ((lane >> 4) & 1) * 16;
    uint32_t aAl = aAh + (OFF_PAL - OFF_PAH);
    uint32_t bRow = (lane & 7) + ((lane >> 4) & 1) * 8;
    uint32_t bColH = ((lane >> 3) & 1) * 16;

    for (int no = 0; no < 2; no++) {
        float acc[16][4];
#pragma unroll
        for (int i = 0; i < 16; i++)
#pragma unroll
            for (int j = 0; j < 4; j++) acc[i][j] = 0.0f;

        for (int kc = 0; kc < 2; kc++) {
            __syncthreads();
            for (int i = t; i < 2048; i += 256) {
                int n = i >> 3, q = i & 7;
                ((uint4*)(sm + OFF_PBH))[n * 9 + q] =
                    ((const uint4*)g_WabHi)[(size_t)(no * 256 + n) * 16 + kc * 8 + q];
                ((uint4*)(sm + OFF_PBL))[n * 9 + q] =
                    ((const uint4*)g_WabLo)[(size_t)(no * 256 + n) * 16 + kc * 8 + q];
            }
            __syncthreads();
#pragma unroll
            for (int ks = 0; ks < 4; ks++) {
                uint32_t kb = (kc * 64 + ks * 16) * 2;
                uint32_t ah[4], al[4];
                LDSM_X4(ah, aAh + kb);
                LDSM_X4(al, aAl + kb);
#pragma unroll
                for (int gp = 0; gp < 8; gp++) {
                    uint32_t baddr = smu + OFF_PBH + (n0 + gp * 16 + bRow) * PB_STRIDE + ks * 32 + bColH;
                    uint32_t bh[4], bl[4];
                    LDSM_X4(bh, baddr);
                    LDSM_X4(bl, baddr + (OFF_PBL - OFF_PBH));
                    MMA16816(acc[gp * 2],     ah, bh[0], bh[1]);
                    MMA16816(acc[gp * 2 + 1], ah, bh[2], bh[3]);
                    MMA16816(acc[gp * 2],     ah, bl[0], bl[1]);
                    MMA16816(acc[gp * 2 + 1], ah, bl[2], bl[3]);
                    MMA16816(acc[gp * 2],     al, bh[0], bh[1]);
                    MMA16816(acc[gp * 2 + 1], al, bh[2], bh[3]);
                }
            }
        }
        float* dst = no ? g_prev : g_preu;
        int r0 = row0 + m0 + g, r1 = r0 + 8;
#pragma unroll
        for (int nt = 0; nt < 16; nt++) {
            int n = n0 + nt * 8 + tq * 2;
            *(float2*)(dst + (size_t)r0 * HID + n) = make_float2(acc[nt][0], acc[nt][1]);
            *(float2*)(dst + (size_t)r1 * HID + n) = make_float2(acc[nt][2], acc[nt][3]);
        }
    }
}

// --------------------------- main pair kernel (mma.sync) -------------------
#define A_STRIDE 528
#define B_STRIDE 144
#define OFF_A1HI 0
#define OFF_A1LO 33792
#define OFF_BHI  67584
#define OFF_BLO  104448
#define OFF_US   141312
#define OFF_VS   141568
#define OFF_DOT  141824
#define OFF_SCC  142848
#define OFF_SCN  143104
#define OFF_SCA  143360
#define OFF_SCR  143616
#define OFF_WEX  143872
#define OFF_B1S  147968
#define OFF_B2S  148992
#define OFF_W3S  149504
#define OFF_SRED 150016
#define SMEM2    150528

// B1 tile prefetch: 8 uint4/thread per hi/lo buffer
__device__ __forceinline__ void ldB1(uint4* rh, uint4* rl, int kc, int t) {
#pragma unroll
    for (int w = 0; w < 8; w++) {
        int i = t + w * 256;
        int n = i >> 3, q = i & 7;
        rh[w] = ((const uint4*)g_B1hi)[n * 32 + kc * 8 + q];
        rl[w] = ((const uint4*)g_B1lo)[n * 32 + kc * 8 + q];
    }
}
__device__ __forceinline__ void stB1(char* sm, const uint4* rh, const uint4* rl, int t) {
#pragma unroll
    for (int w = 0; w < 8; w++) {
        int i = t + w * 256;
        int n = i >> 3, q = i & 7;
        ((uint4*)(sm + OFF_BHI))[n * 9 + q] = rh[w];
        ((uint4*)(sm + OFF_BLO))[n * 9 + q] = rl[w];
    }
}
__device__ __forceinline__ void ldB2(uint4* rh, uint4* rl, int kc, int t) {
#pragma unroll
    for (int w = 0; w < 4; w++) {
        int i = t + w * 256;
        int n = i >> 3, q = i & 7;
        rh[w] = ((const uint4*)g_B2hi)[n * 32 + kc * 8 + q];
        rl[w] = ((const uint4*)g_B2lo)[n * 32 + kc * 8 + q];
    }
}
__device__ __forceinline__ void stB2(char* sm, const uint4* rh, const uint4* rl, int t) {
#pragma unroll
    for (int w = 0; w < 4; w++) {
        int i = t + w * 256;
        int n = i >> 3, q = i & 7;
        ((uint4*)(sm + OFF_BHI))[n * 9 + q] = rh[w];
        ((uint4*)(sm + OFF_BLO))[n * 9 + q] = rl[w];
    }
}

__global__ __launch_bounds__(256, 1) void pair3_kernel(
    const float* __restrict__ x,
    const int* __restrict__ pairs,
    const float* __restrict__ W1,
    const float* __restrict__ b1,
    const float* __restrict__ b2,
    const float* __restrict__ W3,
    const float* __restrict__ b3,
    float* __restrict__ out) {
    extern __shared__ char sm[];
    uint32_t smu = smem_u32(sm);
    char*  A1hi = sm + OFF_A1HI;
    char*  A1lo = sm + OFF_A1LO;
    int*   us   = (int*)(sm + OFF_US);
    int*   vs   = (int*)(sm + OFF_VS);
    float* dotp = (float*)(sm + OFF_DOT);
    float* scC  = (float*)(sm + OFF_SCC);
    float* scN  = (float*)(sm + OFF_SCN);
    float* scA  = (float*)(sm + OFF_SCA);
    float* scR  = (float*)(sm + OFF_SCR);
    float* Wex  = (float*)(sm + OFF_WEX);
    float* b1s  = (float*)(sm + OFF_B1S);
    float* b2s  = (float*)(sm + OFF_B2S);
    float* W3s  = (float*)(sm + OFF_W3S);
    float* sred = (float*)(sm + OFF_SRED);

    int t = threadIdx.x;
    int wid = t >> 5, lane = t & 31;
    int g = lane >> 2, tq = lane & 3;
    int pair0 = blockIdx.x * TBP;

    if (t < TBP) {
        us[t] = pairs[2 * (pair0 + t)];
        vs[t] = pairs[2 * (pair0 + t) + 1];
    }
    for (int i = t; i < 1024; i += 256) Wex[i] = W1[640 * HID + i];
    b1s[t] = b1[t];
    if (t < 128) { b2s[t] = b2[t]; W3s[t] = W3[t]; }
    __syncthreads();

    // ---- Phase A: features -> A1 hi/lo row-major bf16 ---------------------
    {
        int m = t & 63, s = t >> 6;
        const float4* xu4 = (const float4*)(x + (size_t)us[m] * INCH + s * 32);
        const float4* xv4 = (const float4*)(x + (size_t)vs[m] * INCH + s * 32);
        unsigned short* Ah = (unsigned short*)(A1hi + m * A_STRIDE);
        unsigned short* Al = (unsigned short*)(A1lo + m * A_STRIDE);
        float dot = 0.0f;
#pragma unroll
        for (int i = 0; i < 8; i++) {
            float4 a = xu4[i], b = xv4[i];
            int f = s * 32 + i * 4;
            float p0 = a.x * b.x, p1 = a.y * b.y, p2 = a.z * b.z, p3 = a.w * b.w;
            dot += p0 + p1 + p2 + p3;
            unsigned short h0,l0,h1,l1,h2,l2,h3,l3;
            bsplit(p0,h0,l0); bsplit(p1,h1,l1); bsplit(p2,h2,l2); bsplit(p3,h3,l3);
            *(uint2*)(Ah + f)       = make_uint2(pack2(h0,h1), pack2(h2,h3));
            *(uint2*)(Al + f)       = make_uint2(pack2(l0,l1), pack2(l2,l3));
            float q0 = fabsf(a.x-b.x), q1 = fabsf(a.y-b.y), q2 = fabsf(a.z-b.z), q3 = fabsf(a.w-b.w);
            bsplit(q0,h0,l0); bsplit(q1,h1,l1); bsplit(q2,h2,l2); bsplit(q3,h3,l3);
            *(uint2*)(Ah + 128 + f) = make_uint2(pack2(h0,h1), pack2(h2,h3));
            *(uint2*)(Al + 128 + f) = make_uint2(pack2(l0,l1), pack2(l2,l3));
        }
        dotp[s * 64 + m] = dot;
    }
    __syncthreads();
    if (t < TBP) {
        float d = dotp[t] + dotp[64 + t] + dotp[128 + t] + dotp[192 + t];
        float nn = g_norm[us[t]] * g_norm[vs[t]];
        scC[t] = d / fmaxf(nn, EPSF);
    }

    // Prefetch B1 chunk 0 (LDGs overlap with the bitset phase below)
    uint4 pbh[8], pbl[8];
    ldB1(pbh, pbl, 0, t);

    // ---- Phase B: common-neighbor stats (warp per 8 pairs) ----------------
    {
        for (int pp = 0; pp < 8; pp++) {
            int m = wid * 8 + pp;
            const unsigned long long* bu = g_bits + (size_t)us[m] * WORDS;
            const unsigned long long* bv = g_bits + (size_t)vs[m] * WORDS;
            int cn = 0; float aa = 0.0f, ra = 0.0f;
#pragma unroll
            for (int it = 0; it < 4; it++) {
                int wi = it * 32 + lane;
                unsigned long long c = bu[wi] & bv[wi];
                cn += __popcll(c);
                while (c) {
                    int b = __ffsll((long long)c) - 1;
                    c &= c - 1;
                    int idx = wi * 64 + b;
                    aa += g_invlog[idx];
                    ra += g_invdeg[idx];
                }
            }
#pragma unroll
            for (int o = 16; o; o >>= 1) {
                cn += __shfl_xor_sync(0xffffffffu, cn, o);
                aa += __shfl_xor_sync(0xffffffffu, aa, o);
                ra += __shfl_xor_sync(0xffffffffu, ra, o);
            }
            if (lane == 0) { scN[m] = (float)cn; scA[m] = aa; scR[m] = ra; }
        }
    }

    // ---- GEMM1: h1[64x256] via mma.sync, K chunks of 64 -------------------
    int m0 = (wid & 3) * 16;
    int n0 = (wid >> 2) * 128;
    float acc1[16][4];
#pragma unroll
    for (int i = 0; i < 16; i++)
#pragma unroll
        for (int j = 0; j < 4; j++) acc1[i][j] = 0.0f;

    uint32_t aAh = smu + OFF_A1HI + (m0 + (lane & 15)) * A_STRIDE + ((lane >> 4) & 1) * 16;
    uint32_t aAl = aAh + (OFF_A1LO - OFF_A1HI);
    uint32_t bRow = (lane & 7) + ((lane >> 4) & 1) * 8;
    uint32_t bColH = ((lane >> 3) & 1) * 16;

    for (int kc = 0; kc < 4; kc++) {
        __syncthreads();                 // prior chunk's ldsm reads done
        stB1(sm, pbh, pbl, t);
        __syncthreads();
        if (kc < 3) ldB1(pbh, pbl, kc + 1, t);   // hide behind MMAs
#pragma unroll
        for (int ks = 0; ks < 4; ks++) {
            uint32_t kb = (kc * 64 + ks * 16) * 2;
            uint32_t ah[4], al[4];
            LDSM_X4(ah, aAh + kb);
            LDSM_X4(al, aAl + kb);
#pragma unroll
            for (int gp = 0; gp < 8; gp++) {
                uint32_t baddr = smu + OFF_BHI + (n0 + gp * 16 + bRow) * B_STRIDE + ks * 32 + bColH;
                uint32_t bh[4], bl[4];
                LDSM_X4(bh, baddr);
                LDSM_X4(bl, baddr + (OFF_BLO - OFF_BHI));
                // interleaved: alternate even/odd accumulators to break RAW chains
                MMA16816(acc1[gp * 2],     ah, bh[0], bh[1]);
                MMA16816(acc1[gp * 2 + 1], ah, bh[2], bh[3]);
                MMA16816(acc1[gp * 2],     ah, bl[0], bl[1]);
                MMA16816(acc1[gp * 2 + 1], ah, bl[2], bl[3]);
                MMA16816(acc1[gp * 2],     al, bh[0], bh[1]);
                MMA16816(acc1[gp * 2 + 1], al, bh[2], bh[3]);
            }
        }
    }
    __syncthreads();

    // Prefetch B2 chunk 0 (overlaps epilogue1 compute)
    uint4 qbh[4], qbl[4];
    ldB2(qbh, qbl, 0, t);

    // ---- Epilogue1: h1 = relu(D1 + pre_u + pre_v + b1 + scalars) -> A1 ----
    {
        int r0 = m0 + g, r1 = r0 + 8;
        int u0 = us[r0], v0 = vs[r0], u1 = us[r1], v1 = vs[r1];
        float c0m = scC[r0], n0m = scN[r0], a0m = scA[r0], q0m = scR[r0];
        float c1m = scC[r1], n1m = scN[r1], a1m = scA[r1], q1m = scR[r1];
        unsigned short* Ah0 = (unsigned short*)(A1hi + r0 * A_STRIDE);
        unsigned short* Al0 = (unsigned short*)(A1lo + r0 * A_STRIDE);
        unsigned short* Ah1 = (unsigned short*)(A1hi + r1 * A_STRIDE);
        unsigned short* Al1 = (unsigned short*)(A1lo + r1 * A_STRIDE);
#pragma unroll
        for (int nt = 0; nt < 16; nt++) {
            int n = n0 + nt * 8 + tq * 2;
            float2 pu0 = *(const float2*)(g_preu + (size_t)u0 * HID + n);
            float2 pv0 = *(const float2*)(g_prev + (size_t)v0 * HID + n);
            float2 pu1 = *(const float2*)(g_preu + (size_t)u1 * HID + n);
            float2 pv1 = *(const float2*)(g_prev + (size_t)v1 * HID + n);
            float w0a = Wex[n], w0b = Wex[n + 1];
            float w1a = Wex[256 + n], w1b = Wex[256 + n + 1];
            float w2a = Wex[512 + n], w2b = Wex[512 + n + 1];
            float w3a = Wex[768 + n], w3b = Wex[768 + n + 1];
            float ba = b1s[n], bb = b1s[n + 1];
            float h00 = acc1[nt][0] + pu0.x + pv0.x + ba;
            h00 = fmaf(c0m, w0a, h00); h00 = fmaf(n0m, w1a, h00);
            h00 = fmaf(a0m, w2a, h00); h00 = fmaf(q0m, w3a, h00);
            float h01 = acc1[nt][1] + pu0.y + pv0.y + bb;
            h01 = fmaf(c0m, w0b, h01); h01 = fmaf(n0m, w1b, h01);
            h01 = fmaf(a0m, w2b, h01); h01 = fmaf(q0m, w3b, h01);
            float h10 = acc1[nt][2] + pu1.x + pv1.x + ba;
            h10 = fmaf(c1m, w0a, h10); h10 = fmaf(n1m, w1a, h10);
            h10 = fmaf(a1m, w2a, h10); h10 = fmaf(q1m, w3a, h10);
            float h11 = acc1[nt][3] + pu1.y + pv1.y + bb;
            h11 = fmaf(c1m, w0b, h11); h11 = fmaf(n1m, w1b, h11);
            h11 = fmaf(a1m, w2b, h11); h11 = fmaf(q1m, w3b, h11);
            h00 = fmaxf(h00, 0.0f); h01 = fmaxf(h01, 0.0f);
            h10 = fmaxf(h10, 0.0f); h11 = fmaxf(h11, 0.0f);
            unsigned short hh0, ll0, hh1, ll1;
            bsplit(h00, hh0, ll0); bsplit(h01, hh1, ll1);
            *(uint32_t*)(Ah0 + n) = pack2(hh0, hh1);
            *(uint32_t*)(Al0 + n) = pack2(ll0, ll1);
            bsplit(h10, hh0, ll0); bsplit(h11, hh1, ll1);
            *(uint32_t*)(Ah1 + n) = pack2(hh0, hh1);
            *(uint32_t*)(Al1 + n) = pack2(ll0, ll1);
        }
    }

    // ---- GEMM2: h2[64x128] = h1 @ W2 --------------------------------------
    int n02 = (wid >> 2) * 64;
    float acc2[8][4];
#pragma unroll
    for (int i = 0; i < 8; i++)
#pragma unroll
        for (int j = 0; j < 4; j++) acc2[i][j] = 0.0f;

    for (int kc = 0; kc < 4; kc++) {
        __syncthreads();                 // h1 writes (kc=0) / prior ldsm done
        stB2(sm, qbh, qbl, t);
        __syncthreads();
        if (kc < 3) ldB2(qbh, qbl, kc + 1, t);
#pragma unroll
        for (int ks = 0; ks < 4; ks++) {
            uint32_t kb = (kc * 64 + ks * 16) * 2;
            uint32_t ah[4], al[4];
            LDSM_X4(ah, aAh + kb);
            LDSM_X4(al, aAl + kb);
#pragma unroll
            for (int gp = 0; gp < 4; gp++) {
                uint32_t baddr = smu + OFF_BHI + (n02 + gp * 16 + bRow) * B_STRIDE + ks * 32 + bColH;
                uint32_t bh[4], bl[4];
                LDSM_X4(bh, baddr);
                LDSM_X4(bl, baddr + (OFF_BLO - OFF_BHI));
                MMA16816(acc2[gp * 2],     ah, bh[0], bh[1]);
                MMA16816(acc2[gp * 2 + 1], ah, bh[2], bh[3]);
                MMA16816(acc2[gp * 2],     ah, bl[0], bl[1]);
                MMA16816(acc2[gp * 2 + 1], ah, bl[2], bl[3]);
                MMA16816(acc2[gp * 2],     al, bh[0], bh[1]);
                MMA16816(acc2[gp * 2 + 1], al, bh[2], bh[3]);
            }
        }
    }

    // ---- Epilogue2 + GEMV: s = relu(h2+b2) @ W3 + b3 ----------------------
    {
        int r0 = m0 + g, r1 = r0 + 8;
        float s0 = 0.0f, s1 = 0.0f;
#pragma unroll
        for (int nt = 0; nt < 8; nt++) {
            int n = n02 + nt * 8 + tq * 2;
            float w3a = W3s[n], w3b = W3s[n + 1];
            float ba = b2s[n], bb = b2s[n + 1];
            s0 = fmaf(fmaxf(acc2[nt][0] + ba, 0.0f), w3a, s0);
            s0 = fmaf(fmaxf(acc2[nt][1] + bb, 0.0f), w3b, s0);
            s1 = fmaf(fmaxf(acc2[nt][2] + ba, 0.0f), w3a, s1);
            s1 = fmaf(fmaxf(acc2[nt][3] + bb, 0.0f), w3b, s1);
        }
        s0 += __shfl_xor_sync(0xffffffffu, s0, 1);
        s0 += __shfl_xor_sync(0xffffffffu, s0, 2);
        s1 += __shfl_xor_sync(0xffffffffu, s1, 1);
        s1 += __shfl_xor_sync(0xffffffffu, s1, 2);
        if (tq == 0) {
            sred[r0 * 2 + (wid >> 2)] = s0;
            sred[r1 * 2 + (wid >> 2)] = s1;
        }
    }
    __syncthreads();
    if (t < TBP) out[pair0 + t] = sred[t * 2] + sred[t * 2 + 1] + b3[0];
}

// --------------------------- launcher --------------------------------------
extern "C" void kernel_launch(void* const* d_in, const int* in_sizes, int n_in,
                              void* d_out, int out_size) {
    const float* x  = (const float*)d_in[0];
    const int* ei   = (const int*)d_in[1];
    const int* ep   = (const int*)d_in[2];
    const float* W1 = (const float*)d_in[3];
    const float* b1 = (const float*)d_in[4];
    const float* W2 = (const float*)d_in[5];
    const float* b2 = (const float*)d_in[6];
    const float* W3 = (const float*)d_in[7];
    const float* b3 = (const float*)d_in[8];
    float* out      = (float*)d_out;

    int E = in_sizes[1] / 2;
    int P = in_sizes[2] / 2;

    build_bits_kernel<<<(E + 255) / 256, 256>>>(ei, E);
    node_stats_kernel<<<NNODES / 8, 256>>>(x);
    combine_w_kernel<<<128, 256>>>(W1);
    w_split_kernel<<<384, 256>>>(W1, W2);
    x_split_kernel<<<4096, 256>>>(x);
    wab_split_kernel<<<256, 256>>>();

    cudaFuncSetAttribute(pre_mma_kernel,
                         cudaFuncAttributeMaxDynamicSharedMemorySize, SMEM_PRE);
    pre_mma_kernel<<<NNODES / 64, 256, SMEM_PRE>>>();

    cudaFuncSetAttribute(pair3_kernel,
                         cudaFuncAttributeMaxDynamicSharedMemorySize, SMEM2);
    pair3_kernel<<<P / TBP, 256, SMEM2>>>(x, ep, W1, b1, b2, W3, b3, out);
}